// round 3
// baseline (speedup 1.0000x reference)
#include <cuda_runtime.h>
#include <math.h>

#define N_ 4
#define L_ 1024
#define C_ 1024
#define H_ 16
#define HD_ 64
#define R_ 8

// Scratch (static device arrays: no allocation at runtime)
__device__ float g_xa[N_ * L_ * 24];                 // x @ A^T for q,k,v   [row][t*8+r]
__device__ float g_q[N_ * H_ * L_ * HD_];            // [N,H,L,HD]
__device__ float g_k[N_ * H_ * L_ * HD_];
__device__ float g_v[N_ * H_ * L_ * HD_];
__device__ float g_ctx[N_ * L_ * C_];                // attention output, [N,L,C]

// ---------------------------------------------------------------------------
// K1: xa[row, t*8+r] = dot(x[row,:], A_t[r,:])   (24 dots of length 1024/row)
// ---------------------------------------------------------------------------
__global__ void xa_kernel(const float* __restrict__ x,
                          const float* __restrict__ Aq,
                          const float* __restrict__ Ak,
                          const float* __restrict__ Av) {
    __shared__ float xs[C_];
    const int row = blockIdx.x;
    const int tid = threadIdx.x;
    const float* xr = x + (size_t)row * C_;
    for (int i = tid; i < C_; i += 256) xs[i] = xr[i];
    __syncthreads();
    const int w = tid >> 5, lane = tid & 31;
#pragma unroll
    for (int d = 0; d < 3; d++) {
        const int rg = w * 3 + d;            // 0..23
        const int t = rg >> 3, r = rg & 7;
        const float* A = (t == 0 ? Aq : (t == 1 ? Ak : Av)) + r * C_;
        float s = 0.f;
        for (int c = lane; c < C_; c += 32) s += xs[c] * A[c];
#pragma unroll
        for (int o = 16; o > 0; o >>= 1) s += __shfl_xor_sync(0xffffffffu, s, o);
        if (lane == 0) g_xa[row * 24 + rg] = s;
    }
}

// ---------------------------------------------------------------------------
// K2: qkv = x @ W^T + bias + 2 * (xa @ B^T), scattered to [N,H,L,HD] layout.
// BM=BN=64, BK=16, 256 threads, 4x4 micro-tile.
// ---------------------------------------------------------------------------
__global__ void qkv_gemm(const float* __restrict__ X, const float* __restrict__ W,
                         const float* __restrict__ bias,
                         const float* __restrict__ Bq, const float* __restrict__ Bk,
                         const float* __restrict__ Bv) {
    __shared__ float As[16][64];
    __shared__ float Bs[16][64];
    const int tid = threadIdx.x;
    const int tx = tid & 15, ty = tid >> 4;
    const int r0 = blockIdx.y * 64, c0 = blockIdx.x * 64;
    const int lr = tid >> 2, lk = (tid & 3) << 2;

    float acc[4][4];
#pragma unroll
    for (int i = 0; i < 4; i++)
#pragma unroll
        for (int j = 0; j < 4; j++) acc[i][j] = 0.f;

    const float* Ap = X + (size_t)(r0 + lr) * C_ + lk;
    const float* Bp = W + (size_t)(c0 + lr) * C_ + lk;

    for (int k0 = 0; k0 < C_; k0 += 16) {
        float4 a4 = *(const float4*)(Ap + k0);
        float4 b4 = *(const float4*)(Bp + k0);
        __syncthreads();
        As[lk + 0][lr] = a4.x; As[lk + 1][lr] = a4.y;
        As[lk + 2][lr] = a4.z; As[lk + 3][lr] = a4.w;
        Bs[lk + 0][lr] = b4.x; Bs[lk + 1][lr] = b4.y;
        Bs[lk + 2][lr] = b4.z; Bs[lk + 3][lr] = b4.w;
        __syncthreads();
#pragma unroll
        for (int kk = 0; kk < 16; kk++) {
            float4 av = *(const float4*)&As[kk][ty << 2];
            float4 bv = *(const float4*)&Bs[kk][tx << 2];
            float a[4] = {av.x, av.y, av.z, av.w};
            float b[4] = {bv.x, bv.y, bv.z, bv.w};
#pragma unroll
            for (int i = 0; i < 4; i++)
#pragma unroll
                for (int j = 0; j < 4; j++) acc[i][j] += a[i] * b[j];
        }
    }

    // epilogue: bias + LoRA, scatter to head layout
    const int t = c0 >> 10;                               // 0=q,1=k,2=v
    const float* Bl = (t == 0) ? Bq : ((t == 1) ? Bk : Bv);
    float* dst = (t == 0) ? g_q : ((t == 1) ? g_k : g_v);
    const int oc0 = c0 & 1023;
    const int h = oc0 >> 6;
#pragma unroll
    for (int i = 0; i < 4; i++) {
        const int row = r0 + (ty << 2) + i;
        const float* xr = g_xa + row * 24 + t * 8;
        float xa[8];
#pragma unroll
        for (int r = 0; r < 8; r++) xa[r] = xr[r];
        const int n = row >> 10, l = row & 1023;
        float* drow = dst + (((size_t)n * H_ + h) * L_ + l) * HD_;
#pragma unroll
        for (int j = 0; j < 4; j++) {
            const int colo = (tx << 2) + j;
            const int oc = oc0 + colo;
            const float* Br = Bl + oc * 8;
            float lo = 0.f;
#pragma unroll
            for (int r = 0; r < 8; r++) lo += xa[r] * Br[r];
            drow[colo] = acc[i][j] + bias[c0 + colo] + 2.0f * lo;
        }
    }
}

// ---------------------------------------------------------------------------
// K3: in-place L2 normalize rows of 64 (one warp per row); y=0 -> q, y=1 -> k
// ---------------------------------------------------------------------------
__global__ void norm_kernel() {
    float* g = blockIdx.y ? g_k : g_q;
    const int row = blockIdx.x * 8 + (threadIdx.x >> 5);
    const int lane = threadIdx.x & 31;
    float2* p = (float2*)(g + (size_t)row * HD_) + lane;
    float2 v = *p;
    float s = v.x * v.x + v.y * v.y;
#pragma unroll
    for (int o = 16; o > 0; o >>= 1) s += __shfl_xor_sync(0xffffffffu, s, o);
    const float inv = 1.0f / fmaxf(sqrtf(s), 1e-12f);
    v.x *= inv; v.y *= inv;
    *p = v;
}

// ---------------------------------------------------------------------------
// K4: flash attention. One block = (n,h) x 64 q-rows. 16 K/V tiles of 64.
// dynamic smem: Qs[64][64] | KP[64][68] (K tile then P tile) | Vs[64][64]
// Each thread loads a FULL row-quarter: 4 x float4 = 16 floats per 64x64 tile.
// ---------------------------------------------------------------------------
#define ATTN_SMEM_BYTES 50176
__global__ void attn_kernel(const float* __restrict__ logit_scale) {
    extern __shared__ float sm[];
    float* Qs = sm;                    // Qs[d*64 + r], pre-scaled by logit scale
    float* KP = sm + 4096;             // Kst[d*68 + c] / Ps[j*68 + r]
    float* Vs = KP + 64 * 68;          // Vs[j*64 + d]

    const int nh = blockIdx.y;         // n*16 + h
    const int qt = blockIdx.x;         // q tile
    const float* Qb = g_q + (size_t)nh * L_ * HD_ + (size_t)qt * 64 * HD_;
    const float* Kb = g_k + (size_t)nh * L_ * HD_;
    const float* Vb = g_v + (size_t)nh * L_ * HD_;
    const int h = nh & 15;
    const float scale = expf(fminf(logit_scale[h], 4.6051702f));

    const int tid = threadIdx.x;
    const int tx = tid & 15, ty = tid >> 4;
    const int lr = tid >> 2, lk = (tid & 3) << 2;   // row 0..63, col base {0,4,8,12}

    // load Q tile: thread covers cols lk+16*dd, dd=0..3 of row lr
#pragma unroll
    for (int dd = 0; dd < 4; dd++) {
        const int col = lk + dd * 16;
        float4 q4 = *(const float4*)(Qb + lr * HD_ + col);
        Qs[(col + 0) * 64 + lr] = q4.x * scale;
        Qs[(col + 1) * 64 + lr] = q4.y * scale;
        Qs[(col + 2) * 64 + lr] = q4.z * scale;
        Qs[(col + 3) * 64 + lr] = q4.w * scale;
    }

    float o_acc[4][4];
    float m_i[4], l_i[4];
#pragma unroll
    for (int i = 0; i < 4; i++) {
        m_i[i] = -1e30f; l_i[i] = 0.f;
#pragma unroll
        for (int j = 0; j < 4; j++) o_acc[i][j] = 0.f;
    }

    for (int kt = 0; kt < 16; kt++) {
        const float* Kt = Kb + kt * 64 * HD_;
        const float* Vt = Vb + kt * 64 * HD_;
        float4 k4[4], v4[4];
#pragma unroll
        for (int dd = 0; dd < 4; dd++) {
            const int col = lk + dd * 16;
            k4[dd] = *(const float4*)(Kt + lr * HD_ + col);
            v4[dd] = *(const float4*)(Vt + lr * HD_ + col);
        }
        __syncthreads();   // previous PV done with KP/Vs (also covers Qs on iter 0)
#pragma unroll
        for (int dd = 0; dd < 4; dd++) {
            const int col = lk + dd * 16;
            KP[(col + 0) * 68 + lr] = k4[dd].x;
            KP[(col + 1) * 68 + lr] = k4[dd].y;
            KP[(col + 2) * 68 + lr] = k4[dd].z;
            KP[(col + 3) * 68 + lr] = k4[dd].w;
            *(float4*)&Vs[lr * 64 + col] = v4[dd];
        }
        __syncthreads();

        // S = (scale*Qn) @ Kn^T  (4x4 per thread)
        float s[4][4];
#pragma unroll
        for (int i = 0; i < 4; i++)
#pragma unroll
            for (int j = 0; j < 4; j++) s[i][j] = 0.f;
#pragma unroll
        for (int kk = 0; kk < 64; kk++) {
            float4 av = *(const float4*)&Qs[kk * 64 + (ty << 2)];
            float4 bv = *(const float4*)&KP[kk * 68 + (tx << 2)];
            float a[4] = {av.x, av.y, av.z, av.w};
            float b[4] = {bv.x, bv.y, bv.z, bv.w};
#pragma unroll
            for (int i = 0; i < 4; i++)
#pragma unroll
                for (int j = 0; j < 4; j++) s[i][j] += a[i] * b[j];
        }

        // online softmax (row groups = 16 threads sharing ty; butterfly <=8 stays in group)
#pragma unroll
        for (int i = 0; i < 4; i++) {
            float mx = fmaxf(fmaxf(s[i][0], s[i][1]), fmaxf(s[i][2], s[i][3]));
            mx = fmaxf(mx, __shfl_xor_sync(0xffffffffu, mx, 8));
            mx = fmaxf(mx, __shfl_xor_sync(0xffffffffu, mx, 4));
            mx = fmaxf(mx, __shfl_xor_sync(0xffffffffu, mx, 2));
            mx = fmaxf(mx, __shfl_xor_sync(0xffffffffu, mx, 1));
            const float mnew = fmaxf(m_i[i], mx);
            const float corr = __expf(m_i[i] - mnew);
            m_i[i] = mnew;
            float rs = 0.f;
#pragma unroll
            for (int j = 0; j < 4; j++) { s[i][j] = __expf(s[i][j] - mnew); rs += s[i][j]; }
            rs += __shfl_xor_sync(0xffffffffu, rs, 8);
            rs += __shfl_xor_sync(0xffffffffu, rs, 4);
            rs += __shfl_xor_sync(0xffffffffu, rs, 2);
            rs += __shfl_xor_sync(0xffffffffu, rs, 1);
            l_i[i] = l_i[i] * corr + rs;
#pragma unroll
            for (int j = 0; j < 4; j++) o_acc[i][j] *= corr;
        }

        __syncthreads();   // everyone done reading KP as K-tile
#pragma unroll
        for (int i = 0; i < 4; i++)
#pragma unroll
            for (int j = 0; j < 4; j++)
                KP[((tx << 2) + j) * 68 + (ty << 2) + i] = s[i][j];
        __syncthreads();

        // O += P @ V
#pragma unroll
        for (int j = 0; j < 64; j++) {
            float4 p = *(const float4*)&KP[j * 68 + (ty << 2)];
            float4 v = *(const float4*)&Vs[j * 64 + (tx << 2)];
            float pi[4] = {p.x, p.y, p.z, p.w};
            float vv[4] = {v.x, v.y, v.z, v.w};
#pragma unroll
            for (int i = 0; i < 4; i++)
#pragma unroll
                for (int jj = 0; jj < 4; jj++) o_acc[i][jj] += pi[i] * vv[jj];
        }
    }

    const int n = nh >> 4;
#pragma unroll
    for (int i = 0; i < 4; i++) {
        const float inv = 1.0f / l_i[i];
        const int l = qt * 64 + (ty << 2) + i;
        float4 o;
        o.x = o_acc[i][0] * inv; o.y = o_acc[i][1] * inv;
        o.z = o_acc[i][2] * inv; o.w = o_acc[i][3] * inv;
        *(float4*)&g_ctx[((size_t)(n * L_ + l)) * C_ + h * HD_ + (tx << 2)] = o;
    }
}

// ---------------------------------------------------------------------------
// K5: out = ctx @ Wo^T + bo   (same tiling as K2, no LoRA)
// ---------------------------------------------------------------------------
__global__ void out_gemm(const float* __restrict__ Wo, const float* __restrict__ bo,
                         float* __restrict__ out) {
    __shared__ float As[16][64];
    __shared__ float Bs[16][64];
    const int tid = threadIdx.x;
    const int tx = tid & 15, ty = tid >> 4;
    const int r0 = blockIdx.y * 64, c0 = blockIdx.x * 64;
    const int lr = tid >> 2, lk = (tid & 3) << 2;

    float acc[4][4];
#pragma unroll
    for (int i = 0; i < 4; i++)
#pragma unroll
        for (int j = 0; j < 4; j++) acc[i][j] = 0.f;

    const float* Ap = g_ctx + (size_t)(r0 + lr) * C_ + lk;
    const float* Bp = Wo + (size_t)(c0 + lr) * C_ + lk;

    for (int k0 = 0; k0 < C_; k0 += 16) {
        float4 a4 = *(const float4*)(Ap + k0);
        float4 b4 = *(const float4*)(Bp + k0);
        __syncthreads();
        As[lk + 0][lr] = a4.x; As[lk + 1][lr] = a4.y;
        As[lk + 2][lr] = a4.z; As[lk + 3][lr] = a4.w;
        Bs[lk + 0][lr] = b4.x; Bs[lk + 1][lr] = b4.y;
        Bs[lk + 2][lr] = b4.z; Bs[lk + 3][lr] = b4.w;
        __syncthreads();
#pragma unroll
        for (int kk = 0; kk < 16; kk++) {
            float4 av = *(const float4*)&As[kk][ty << 2];
            float4 bv = *(const float4*)&Bs[kk][tx << 2];
            float a[4] = {av.x, av.y, av.z, av.w};
            float b[4] = {bv.x, bv.y, bv.z, bv.w};
#pragma unroll
            for (int i = 0; i < 4; i++)
#pragma unroll
                for (int j = 0; j < 4; j++) acc[i][j] += a[i] * b[j];
        }
    }
#pragma unroll
    for (int i = 0; i < 4; i++) {
        const int row = r0 + (ty << 2) + i;
#pragma unroll
        for (int j = 0; j < 4; j++) {
            const int col = c0 + (tx << 2) + j;
            out[(size_t)row * C_ + col] = acc[i][j] + bo[col];
        }
    }
}

// ---------------------------------------------------------------------------
extern "C" void kernel_launch(void* const* d_in, const int* in_sizes, int n_in,
                              void* d_out, int out_size) {
    (void)in_sizes; (void)n_in; (void)out_size;
    const float* x    = (const float*)d_in[0];
    const float* W    = (const float*)d_in[1];
    const float* bias = (const float*)d_in[2];
    const float* Aq   = (const float*)d_in[3];
    const float* Bq   = (const float*)d_in[4];
    const float* Ak   = (const float*)d_in[5];
    const float* Bk   = (const float*)d_in[6];
    const float* Av   = (const float*)d_in[7];
    const float* Bv   = (const float*)d_in[8];
    const float* ls   = (const float*)d_in[9];
    const float* Wo   = (const float*)d_in[10];
    const float* bo   = (const float*)d_in[11];
    float* out = (float*)d_out;

    cudaFuncSetAttribute(attn_kernel, cudaFuncAttributeMaxDynamicSharedMemorySize,
                         ATTN_SMEM_BYTES);

    xa_kernel<<<N_ * L_, 256>>>(x, Aq, Ak, Av);
    qkv_gemm<<<dim3(48, 64), 256>>>(x, W, bias, Bq, Bk, Bv);
    norm_kernel<<<dim3((N_ * H_ * L_) / 8, 2), 256>>>();
    attn_kernel<<<dim3(16, 64), 256, ATTN_SMEM_BYTES>>>(ls);
    out_gemm<<<dim3(16, 64), 256>>>(Wo, bo, out);
}

// round 8
// speedup vs baseline: 1.0766x; 1.0766x over previous
#include <cuda_runtime.h>
#include <math.h>

#define N_ 4
#define L_ 1024
#define C_ 1024
#define H_ 16
#define HD_ 64
#define R_ 8

typedef unsigned long long ull;

// Scratch (static device arrays: no allocation at runtime)
__device__ float g_xa[N_ * L_ * 24];                 // x @ A^T for q,k,v   [row][t*8+r]
__device__ float g_q[N_ * H_ * L_ * HD_];            // [N,H,L,HD]
__device__ float g_k[N_ * H_ * L_ * HD_];
__device__ float g_v[N_ * H_ * L_ * HD_];
__device__ float g_ctx[N_ * L_ * C_];                // attention output, [N,L,C]

// packed fp32x2 helpers
__device__ __forceinline__ void fma2(ull& d, ull a, ull b) {
    asm("fma.rn.f32x2 %0, %1, %2, %0;" : "+l"(d) : "l"(a), "l"(b));
}
__device__ __forceinline__ ull pack2(float x) {
    ull r; asm("mov.b64 %0, {%1, %1};" : "=l"(r) : "f"(x)); return r;
}
__device__ __forceinline__ void unpack2(float& lo, float& hi, ull v) {
    asm("mov.b64 {%0, %1}, %2;" : "=f"(lo), "=f"(hi) : "l"(v));
}

// ---------------------------------------------------------------------------
// K1: xa[row, t*8+r] = dot(x[row,:], A_t[r,:]) ; 8 rows per block, warp/row
// ---------------------------------------------------------------------------
__global__ void xa_kernel(const float* __restrict__ x,
                          const float* __restrict__ Aq,
                          const float* __restrict__ Ak,
                          const float* __restrict__ Av) {
    __shared__ float4 xs4[8][256];
    const int tid = threadIdx.x;
    const int row0 = blockIdx.x * 8;
    const float4* xg = (const float4*)(x + (size_t)row0 * C_);
    for (int i = tid; i < 2048; i += 256) xs4[i >> 8][i & 255] = xg[i];
    __syncthreads();
    const int w = tid >> 5, lane = tid & 31;
#pragma unroll 1
    for (int d = 0; d < 24; d++) {
        const float* A = (d < 8 ? Aq : (d < 16 ? Ak : Av)) + (d & 7) * C_;
        const float4* A4 = (const float4*)A;
        float s = 0.f;
#pragma unroll
        for (int i = 0; i < 8; i++) {
            float4 a = A4[lane + i * 32];
            float4 xv = xs4[w][lane + i * 32];
            s += a.x * xv.x + a.y * xv.y + a.z * xv.z + a.w * xv.w;
        }
#pragma unroll
        for (int o = 16; o > 0; o >>= 1) s += __shfl_xor_sync(0xffffffffu, s, o);
        if (lane == 0) g_xa[(row0 + w) * 24 + d] = s;
    }
}

// ---------------------------------------------------------------------------
// K2: qkv = x @ W^T + bias + 2*(xa @ B^T) -> [N,H,L,HD].
// BM=BN=128, BK=16, 256 threads, 8x8 micro-tile (split 4+4), f32x2 FMA.
// ---------------------------------------------------------------------------
__global__ void __launch_bounds__(256) qkv_gemm(
        const float* __restrict__ X, const float* __restrict__ W,
        const float* __restrict__ bias,
        const float* __restrict__ Bq, const float* __restrict__ Bk,
        const float* __restrict__ Bv) {
    __shared__ float As[16][132];
    __shared__ float Bs[16][132];
    const int tid = threadIdx.x;
    const int tx = tid & 15, ty = tid >> 4;
    const int r0 = blockIdx.y * 128, c0 = blockIdx.x * 128;
    const int lr = tid >> 2, lk = (tid & 3) << 2;

    ull acc[8][4];
#pragma unroll
    for (int i = 0; i < 8; i++)
#pragma unroll
        for (int j = 0; j < 4; j++) acc[i][j] = 0ULL;

    const float* Ap0 = X + (size_t)(r0 + lr) * C_ + lk;
    const float* Ap1 = Ap0 + (size_t)64 * C_;
    const float* Bp0 = W + (size_t)(c0 + lr) * C_ + lk;
    const float* Bp1 = Bp0 + (size_t)64 * C_;

    for (int k0 = 0; k0 < C_; k0 += 16) {
        float4 a0 = *(const float4*)(Ap0 + k0);
        float4 a1 = *(const float4*)(Ap1 + k0);
        float4 b0 = *(const float4*)(Bp0 + k0);
        float4 b1 = *(const float4*)(Bp1 + k0);
        __syncthreads();
        As[lk + 0][lr] = a0.x; As[lk + 1][lr] = a0.y;
        As[lk + 2][lr] = a0.z; As[lk + 3][lr] = a0.w;
        As[lk + 0][lr + 64] = a1.x; As[lk + 1][lr + 64] = a1.y;
        As[lk + 2][lr + 64] = a1.z; As[lk + 3][lr + 64] = a1.w;
        Bs[lk + 0][lr] = b0.x; Bs[lk + 1][lr] = b0.y;
        Bs[lk + 2][lr] = b0.z; Bs[lk + 3][lr] = b0.w;
        Bs[lk + 0][lr + 64] = b1.x; Bs[lk + 1][lr + 64] = b1.y;
        Bs[lk + 2][lr + 64] = b1.z; Bs[lk + 3][lr + 64] = b1.w;
        __syncthreads();
#pragma unroll
        for (int kk = 0; kk < 16; kk++) {
            float4 av0 = *(const float4*)&As[kk][ty << 2];
            float4 av1 = *(const float4*)&As[kk][(ty << 2) + 64];
            ulonglong2 bv0 = *(const ulonglong2*)&Bs[kk][tx << 2];
            ulonglong2 bv1 = *(const ulonglong2*)&Bs[kk][(tx << 2) + 64];
            ull A[8];
            A[0] = pack2(av0.x); A[1] = pack2(av0.y);
            A[2] = pack2(av0.z); A[3] = pack2(av0.w);
            A[4] = pack2(av1.x); A[5] = pack2(av1.y);
            A[6] = pack2(av1.z); A[7] = pack2(av1.w);
#pragma unroll
            for (int i = 0; i < 8; i++) {
                fma2(acc[i][0], A[i], bv0.x);
                fma2(acc[i][1], A[i], bv0.y);
                fma2(acc[i][2], A[i], bv1.x);
                fma2(acc[i][3], A[i], bv1.y);
            }
        }
    }

    // epilogue: bias + LoRA, scatter to [N,H,L,HD]
    const int t = c0 >> 10;                               // 0=q,1=k,2=v
    const float* Bl = (t == 0) ? Bq : ((t == 1) ? Bk : Bv);
    float* dst = (t == 0) ? g_q : ((t == 1) ? g_k : g_v);
    const int oc0 = c0 & 1023;
    const int h0 = oc0 >> 6;
    const int d0 = tx << 2;
#pragma unroll
    for (int i = 0; i < 8; i++) {
        const int row = r0 + (ty << 2) + (i & 3) + ((i >> 2) << 6);
        const int n = row >> 10, l = row & 1023;
        const float* xr = g_xa + row * 24 + t * 8;
        float xa[8];
#pragma unroll
        for (int r = 0; r < 8; r++) xa[r] = xr[r];
#pragma unroll
        for (int jh = 0; jh < 2; jh++) {
            const int h = h0 + jh;
            float vals[4];
#pragma unroll
            for (int jp = 0; jp < 2; jp++) {
                float lo, hi;
                unpack2(lo, hi, acc[i][jh * 2 + jp]);
                vals[jp * 2 + 0] = lo;
                vals[jp * 2 + 1] = hi;
            }
#pragma unroll
            for (int j = 0; j < 4; j++) {
                const int col  = c0 + jh * 64 + d0 + j;   // global qkv column (bias)
                const int ocol = oc0 + jh * 64 + d0 + j;  // local column within type (LoRA B)
                const float* Br = Bl + (size_t)ocol * 8;
                float lo = 0.f;
#pragma unroll
                for (int r = 0; r < 8; r++) lo += xa[r] * Br[r];
                vals[j] += bias[col] + 2.0f * lo;
            }
            float* drow = dst + (((size_t)n * H_ + h) * L_ + l) * HD_ + d0;
            *(float4*)drow = make_float4(vals[0], vals[1], vals[2], vals[3]);
        }
    }
}

// ---------------------------------------------------------------------------
// K3: in-place L2 normalize rows of 64 (one warp per row); y=0 -> q, y=1 -> k
// ---------------------------------------------------------------------------
__global__ void norm_kernel() {
    float* g = blockIdx.y ? g_k : g_q;
    const int row = blockIdx.x * 8 + (threadIdx.x >> 5);
    const int lane = threadIdx.x & 31;
    float2* p = (float2*)(g + (size_t)row * HD_) + lane;
    float2 v = *p;
    float s = v.x * v.x + v.y * v.y;
#pragma unroll
    for (int o = 16; o > 0; o >>= 1) s += __shfl_xor_sync(0xffffffffu, s, o);
    const float inv = 1.0f / fmaxf(sqrtf(s), 1e-12f);
    v.x *= inv; v.y *= inv;
    *p = v;
}

// ---------------------------------------------------------------------------
// K4: flash attention. 128 threads, 64q x 64k tiles, 8q x 4k micro-tile.
// smem: Qs[64d][68] | KP (K^T [64d][68], then P row-major [64q][68]) | Vs[64l][68]
// ---------------------------------------------------------------------------
#define ATTN_SMEM_BYTES (3 * 64 * 68 * 4)
__global__ void __launch_bounds__(128, 4) attn_kernel(const float* __restrict__ logit_scale) {
    extern __shared__ float sm[];
    float* Qs = sm;
    float* KP = sm + 64 * 68;
    float* Vs = sm + 2 * 64 * 68;

    const int nh = blockIdx.y;         // n*16 + h
    const int qt = blockIdx.x;         // q tile
    const float* Qb = g_q + ((size_t)nh * L_ + qt * 64) * HD_;
    const float* Kb = g_k + (size_t)nh * L_ * HD_;
    const float* Vb = g_v + (size_t)nh * L_ * HD_;
    const float scale = expf(fminf(logit_scale[nh & 15], 4.6051702f));

    const int tid = threadIdx.x;
    const int tx = tid & 15, ty = tid >> 4;       // tx: 4 k-cols / d-cols, ty: 8 q-rows
    const int lr = tid & 63, half = (tid >> 6) * 32;
    const int row_lo = ty << 2;

    // load Q tile, transpose + scale
#pragma unroll
    for (int dd = 0; dd < 8; dd++) {
        const int c = half + dd * 4;
        float4 q4 = *(const float4*)(Qb + lr * HD_ + c);
        Qs[(c + 0) * 68 + lr] = q4.x * scale;
        Qs[(c + 1) * 68 + lr] = q4.y * scale;
        Qs[(c + 2) * 68 + lr] = q4.z * scale;
        Qs[(c + 3) * 68 + lr] = q4.w * scale;
    }

    float o_acc[8][4], m_i[8], l_i[8];
#pragma unroll
    for (int i = 0; i < 8; i++) {
        m_i[i] = -1e30f; l_i[i] = 0.f;
#pragma unroll
        for (int j = 0; j < 4; j++) o_acc[i][j] = 0.f;
    }

    for (int kt = 0; kt < 16; kt++) {
        float4 kb[8], vb[8];
        const float* Krow = Kb + (size_t)(kt * 64 + lr) * HD_ + half;
        const float* Vrow = Vb + (size_t)(kt * 64 + lr) * HD_ + half;
#pragma unroll
        for (int dd = 0; dd < 8; dd++) {
            kb[dd] = *(const float4*)(Krow + dd * 4);
            vb[dd] = *(const float4*)(Vrow + dd * 4);
        }
        __syncthreads();   // previous iteration's PV done with KP(P)/Vs; Qs on iter 0
#pragma unroll
        for (int dd = 0; dd < 8; dd++) {
            const int c = half + dd * 4;
            KP[(c + 0) * 68 + lr] = kb[dd].x;
            KP[(c + 1) * 68 + lr] = kb[dd].y;
            KP[(c + 2) * 68 + lr] = kb[dd].z;
            KP[(c + 3) * 68 + lr] = kb[dd].w;
            *(float4*)&Vs[lr * 68 + c] = vb[dd];
        }
        __syncthreads();

        // S = Qs^T(scaled) @ K  (8x4 per thread)
        float s[8][4];
#pragma unroll
        for (int i = 0; i < 8; i++)
#pragma unroll
            for (int j = 0; j < 4; j++) s[i][j] = 0.f;
#pragma unroll
        for (int kk = 0; kk < 64; kk++) {
            const float* qr = &Qs[kk * 68];
            float4 a0 = *(const float4*)(qr + row_lo);
            float4 a1 = *(const float4*)(qr + row_lo + 32);
            float4 b  = *(const float4*)&KP[kk * 68 + (tx << 2)];
            float a[8] = {a0.x, a0.y, a0.z, a0.w, a1.x, a1.y, a1.z, a1.w};
            float bb[4] = {b.x, b.y, b.z, b.w};
#pragma unroll
            for (int i = 0; i < 8; i++)
#pragma unroll
                for (int j = 0; j < 4; j++) s[i][j] += a[i] * bb[j];
        }

        // online softmax (16 threads sharing ty own a row; xor<=8 stays in group)
#pragma unroll
        for (int i = 0; i < 8; i++) {
            float mx = fmaxf(fmaxf(s[i][0], s[i][1]), fmaxf(s[i][2], s[i][3]));
            mx = fmaxf(mx, __shfl_xor_sync(0xffffffffu, mx, 8));
            mx = fmaxf(mx, __shfl_xor_sync(0xffffffffu, mx, 4));
            mx = fmaxf(mx, __shfl_xor_sync(0xffffffffu, mx, 2));
            mx = fmaxf(mx, __shfl_xor_sync(0xffffffffu, mx, 1));
            const float mnew = fmaxf(m_i[i], mx);
            const float corr = __expf(m_i[i] - mnew);
            m_i[i] = mnew;
            float rs = 0.f;
#pragma unroll
            for (int j = 0; j < 4; j++) { s[i][j] = __expf(s[i][j] - mnew); rs += s[i][j]; }
            rs += __shfl_xor_sync(0xffffffffu, rs, 8);
            rs += __shfl_xor_sync(0xffffffffu, rs, 4);
            rs += __shfl_xor_sync(0xffffffffu, rs, 2);
            rs += __shfl_xor_sync(0xffffffffu, rs, 1);
            l_i[i] = l_i[i] * corr + rs;
#pragma unroll
            for (int j = 0; j < 4; j++) o_acc[i][j] *= corr;
        }

        __syncthreads();   // all warps done reading KP as K-tile
        // P row-major: P[qrow][kcol], conflict-free float4 stores
#pragma unroll
        for (int i = 0; i < 8; i++) {
            const int qr = row_lo + (i & 3) + ((i >> 2) << 5);
            *(float4*)&KP[qr * 68 + (tx << 2)] =
                make_float4(s[i][0], s[i][1], s[i][2], s[i][3]);
        }
        __syncthreads();

        // O += P @ V  (j blocked by 4; p reads broadcast, v conflict-free)
#pragma unroll
        for (int j0 = 0; j0 < 64; j0 += 4) {
            float4 p4[8];
#pragma unroll
            for (int i = 0; i < 8; i++) {
                const int qr = row_lo + (i & 3) + ((i >> 2) << 5);
                p4[i] = *(const float4*)&KP[qr * 68 + j0];
            }
            float4 v4[4];
#pragma unroll
            for (int t = 0; t < 4; t++)
                v4[t] = *(const float4*)&Vs[(j0 + t) * 68 + (tx << 2)];
#pragma unroll
            for (int i = 0; i < 8; i++) {
                float pv[4] = {p4[i].x, p4[i].y, p4[i].z, p4[i].w};
#pragma unroll
                for (int t = 0; t < 4; t++) {
                    float vv[4] = {v4[t].x, v4[t].y, v4[t].z, v4[t].w};
#pragma unroll
                    for (int j = 0; j < 4; j++) o_acc[i][j] += pv[t] * vv[j];
                }
            }
        }
    }

    const int n = nh >> 4, h = nh & 15;
#pragma unroll
    for (int i = 0; i < 8; i++) {
        const int qr = row_lo + (i & 3) + ((i >> 2) << 5);
        const int l = qt * 64 + qr;
        const float inv = 1.0f / l_i[i];
        float4 o = make_float4(o_acc[i][0] * inv, o_acc[i][1] * inv,
                               o_acc[i][2] * inv, o_acc[i][3] * inv);
        *(float4*)&g_ctx[((size_t)(n * L_ + l)) * C_ + h * 64 + (tx << 2)] = o;
    }
}

// ---------------------------------------------------------------------------
// K5: out = ctx @ Wo^T + bo  (same 128x128x16 f32x2 scheme, no LoRA)
// ---------------------------------------------------------------------------
__global__ void __launch_bounds__(256) out_gemm(
        const float* __restrict__ Wo, const float* __restrict__ bo,
        float* __restrict__ out) {
    __shared__ float As[16][132];
    __shared__ float Bs[16][132];
    const int tid = threadIdx.x;
    const int tx = tid & 15, ty = tid >> 4;
    const int r0 = blockIdx.y * 128, c0 = blockIdx.x * 128;
    const int lr = tid >> 2, lk = (tid & 3) << 2;

    ull acc[8][4];
#pragma unroll
    for (int i = 0; i < 8; i++)
#pragma unroll
        for (int j = 0; j < 4; j++) acc[i][j] = 0ULL;

    const float* Ap0 = g_ctx + (size_t)(r0 + lr) * C_ + lk;
    const float* Ap1 = Ap0 + (size_t)64 * C_;
    const float* Bp0 = Wo + (size_t)(c0 + lr) * C_ + lk;
    const float* Bp1 = Bp0 + (size_t)64 * C_;

    for (int k0 = 0; k0 < C_; k0 += 16) {
        float4 a0 = *(const float4*)(Ap0 + k0);
        float4 a1 = *(const float4*)(Ap1 + k0);
        float4 b0 = *(const float4*)(Bp0 + k0);
        float4 b1 = *(const float4*)(Bp1 + k0);
        __syncthreads();
        As[lk + 0][lr] = a0.x; As[lk + 1][lr] = a0.y;
        As[lk + 2][lr] = a0.z; As[lk + 3][lr] = a0.w;
        As[lk + 0][lr + 64] = a1.x; As[lk + 1][lr + 64] = a1.y;
        As[lk + 2][lr + 64] = a1.z; As[lk + 3][lr + 64] = a1.w;
        Bs[lk + 0][lr] = b0.x; Bs[lk + 1][lr] = b0.y;
        Bs[lk + 2][lr] = b0.z; Bs[lk + 3][lr] = b0.w;
        Bs[lk + 0][lr + 64] = b1.x; Bs[lk + 1][lr + 64] = b1.y;
        Bs[lk + 2][lr + 64] = b1.z; Bs[lk + 3][lr + 64] = b1.w;
        __syncthreads();
#pragma unroll
        for (int kk = 0; kk < 16; kk++) {
            float4 av0 = *(const float4*)&As[kk][ty << 2];
            float4 av1 = *(const float4*)&As[kk][(ty << 2) + 64];
            ulonglong2 bv0 = *(const ulonglong2*)&Bs[kk][tx << 2];
            ulonglong2 bv1 = *(const ulonglong2*)&Bs[kk][(tx << 2) + 64];
            ull A[8];
            A[0] = pack2(av0.x); A[1] = pack2(av0.y);
            A[2] = pack2(av0.z); A[3] = pack2(av0.w);
            A[4] = pack2(av1.x); A[5] = pack2(av1.y);
            A[6] = pack2(av1.z); A[7] = pack2(av1.w);
#pragma unroll
            for (int i = 0; i < 8; i++) {
                fma2(acc[i][0], A[i], bv0.x);
                fma2(acc[i][1], A[i], bv0.y);
                fma2(acc[i][2], A[i], bv1.x);
                fma2(acc[i][3], A[i], bv1.y);
            }
        }
    }
#pragma unroll
    for (int i = 0; i < 8; i++) {
        const int row = r0 + (ty << 2) + (i & 3) + ((i >> 2) << 6);
#pragma unroll
        for (int jh = 0; jh < 2; jh++) {
            const int col = c0 + jh * 64 + (tx << 2);
            float vals[4];
#pragma unroll
            for (int jp = 0; jp < 2; jp++) {
                float lo, hi;
                unpack2(lo, hi, acc[i][jh * 2 + jp]);
                vals[jp * 2 + 0] = lo;
                vals[jp * 2 + 1] = hi;
            }
#pragma unroll
            for (int j = 0; j < 4; j++) vals[j] += bo[col + j];
            *(float4*)&out[(size_t)row * C_ + col] =
                make_float4(vals[0], vals[1], vals[2], vals[3]);
        }
    }
}

// ---------------------------------------------------------------------------
extern "C" void kernel_launch(void* const* d_in, const int* in_sizes, int n_in,
                              void* d_out, int out_size) {
    (void)in_sizes; (void)n_in; (void)out_size;
    const float* x    = (const float*)d_in[0];
    const float* W    = (const float*)d_in[1];
    const float* bias = (const float*)d_in[2];
    const float* Aq   = (const float*)d_in[3];
    const float* Bq   = (const float*)d_in[4];
    const float* Ak   = (const float*)d_in[5];
    const float* Bk   = (const float*)d_in[6];
    const float* Av   = (const float*)d_in[7];
    const float* Bv   = (const float*)d_in[8];
    const float* ls   = (const float*)d_in[9];
    const float* Wo   = (const float*)d_in[10];
    const float* bo   = (const float*)d_in[11];
    float* out = (float*)d_out;

    cudaFuncSetAttribute(attn_kernel, cudaFuncAttributeMaxDynamicSharedMemorySize,
                         ATTN_SMEM_BYTES);

    xa_kernel<<<N_ * L_ / 8, 256>>>(x, Aq, Ak, Av);
    qkv_gemm<<<dim3(24, 32), 256>>>(x, W, bias, Bq, Bk, Bv);
    norm_kernel<<<dim3((N_ * H_ * L_) / 8, 2), 256>>>();
    attn_kernel<<<dim3(16, 64), 128, ATTN_SMEM_BYTES>>>(ls);
    out_gemm<<<dim3(8, 32), 256>>>(Wo, bo, out);
}

// round 9
// speedup vs baseline: 1.2404x; 1.1522x over previous
#include <cuda_runtime.h>
#include <math.h>

#define N_ 4
#define L_ 1024
#define C_ 1024
#define H_ 16
#define HD_ 64
#define R_ 8

typedef unsigned long long ull;

// Scratch (static device arrays: no allocation at runtime)
__device__ float g_xa[N_ * L_ * 24];                 // x @ A^T for q,k,v   [row][t*8+r]
__device__ float g_q[N_ * H_ * L_ * HD_];            // [N,H,L,HD]
__device__ float g_k[N_ * H_ * L_ * HD_];
__device__ float g_v[N_ * H_ * L_ * HD_];
__device__ float g_ctx[N_ * L_ * C_];                // attention output, [N,L,C]

// packed fp32x2 helpers
__device__ __forceinline__ void fma2(ull& d, ull a, ull b) {
    asm("fma.rn.f32x2 %0, %1, %2, %0;" : "+l"(d) : "l"(a), "l"(b));
}
__device__ __forceinline__ void mul2(ull& d, ull b) {
    asm("mul.rn.f32x2 %0, %0, %1;" : "+l"(d) : "l"(b));
}
__device__ __forceinline__ ull pack2(float x) {
    ull r; asm("mov.b64 %0, {%1, %1};" : "=l"(r) : "f"(x)); return r;
}
__device__ __forceinline__ void unpack2(float& lo, float& hi, ull v) {
    asm("mov.b64 {%0, %1}, %2;" : "=f"(lo), "=f"(hi) : "l"(v));
}

// ---------------------------------------------------------------------------
// K1: xa[row, t*8+r] = dot(x[row,:], A_t[r,:]) ; 8 rows per block, warp/row
// ---------------------------------------------------------------------------
__global__ void xa_kernel(const float* __restrict__ x,
                          const float* __restrict__ Aq,
                          const float* __restrict__ Ak,
                          const float* __restrict__ Av) {
    __shared__ float4 xs4[8][256];
    const int tid = threadIdx.x;
    const int row0 = blockIdx.x * 8;
    const float4* xg = (const float4*)(x + (size_t)row0 * C_);
    for (int i = tid; i < 2048; i += 256) xs4[i >> 8][i & 255] = xg[i];
    __syncthreads();
    const int w = tid >> 5, lane = tid & 31;
#pragma unroll 1
    for (int d = 0; d < 24; d++) {
        const float* A = (d < 8 ? Aq : (d < 16 ? Ak : Av)) + (d & 7) * C_;
        const float4* A4 = (const float4*)A;
        float s = 0.f;
#pragma unroll
        for (int i = 0; i < 8; i++) {
            float4 a = A4[lane + i * 32];
            float4 xv = xs4[w][lane + i * 32];
            s += a.x * xv.x + a.y * xv.y + a.z * xv.z + a.w * xv.w;
        }
#pragma unroll
        for (int o = 16; o > 0; o >>= 1) s += __shfl_xor_sync(0xffffffffu, s, o);
        if (lane == 0) g_xa[(row0 + w) * 24 + d] = s;
    }
}

// ---------------------------------------------------------------------------
// K2: qkv = x @ W^T + bias + 2*(xa @ B^T) -> [N,H,L,HD].
// BM=BN=128, BK=16, 256 threads, 8x8 micro-tile (split 4+4), f32x2 FMA.
// ---------------------------------------------------------------------------
__global__ void __launch_bounds__(256) qkv_gemm(
        const float* __restrict__ X, const float* __restrict__ W,
        const float* __restrict__ bias,
        const float* __restrict__ Bq, const float* __restrict__ Bk,
        const float* __restrict__ Bv) {
    __shared__ float As[16][132];
    __shared__ float Bs[16][132];
    const int tid = threadIdx.x;
    const int tx = tid & 15, ty = tid >> 4;
    const int r0 = blockIdx.y * 128, c0 = blockIdx.x * 128;
    const int lr = tid >> 2, lk = (tid & 3) << 2;

    ull acc[8][4];
#pragma unroll
    for (int i = 0; i < 8; i++)
#pragma unroll
        for (int j = 0; j < 4; j++) acc[i][j] = 0ULL;

    const float* Ap0 = X + (size_t)(r0 + lr) * C_ + lk;
    const float* Ap1 = Ap0 + (size_t)64 * C_;
    const float* Bp0 = W + (size_t)(c0 + lr) * C_ + lk;
    const float* Bp1 = Bp0 + (size_t)64 * C_;

    for (int k0 = 0; k0 < C_; k0 += 16) {
        float4 a0 = *(const float4*)(Ap0 + k0);
        float4 a1 = *(const float4*)(Ap1 + k0);
        float4 b0 = *(const float4*)(Bp0 + k0);
        float4 b1 = *(const float4*)(Bp1 + k0);
        __syncthreads();
        As[lk + 0][lr] = a0.x; As[lk + 1][lr] = a0.y;
        As[lk + 2][lr] = a0.z; As[lk + 3][lr] = a0.w;
        As[lk + 0][lr + 64] = a1.x; As[lk + 1][lr + 64] = a1.y;
        As[lk + 2][lr + 64] = a1.z; As[lk + 3][lr + 64] = a1.w;
        Bs[lk + 0][lr] = b0.x; Bs[lk + 1][lr] = b0.y;
        Bs[lk + 2][lr] = b0.z; Bs[lk + 3][lr] = b0.w;
        Bs[lk + 0][lr + 64] = b1.x; Bs[lk + 1][lr + 64] = b1.y;
        Bs[lk + 2][lr + 64] = b1.z; Bs[lk + 3][lr + 64] = b1.w;
        __syncthreads();
#pragma unroll
        for (int kk = 0; kk < 16; kk++) {
            float4 av0 = *(const float4*)&As[kk][ty << 2];
            float4 av1 = *(const float4*)&As[kk][(ty << 2) + 64];
            ulonglong2 bv0 = *(const ulonglong2*)&Bs[kk][tx << 2];
            ulonglong2 bv1 = *(const ulonglong2*)&Bs[kk][(tx << 2) + 64];
            ull A[8];
            A[0] = pack2(av0.x); A[1] = pack2(av0.y);
            A[2] = pack2(av0.z); A[3] = pack2(av0.w);
            A[4] = pack2(av1.x); A[5] = pack2(av1.y);
            A[6] = pack2(av1.z); A[7] = pack2(av1.w);
#pragma unroll
            for (int i = 0; i < 8; i++) {
                fma2(acc[i][0], A[i], bv0.x);
                fma2(acc[i][1], A[i], bv0.y);
                fma2(acc[i][2], A[i], bv1.x);
                fma2(acc[i][3], A[i], bv1.y);
            }
        }
    }

    // epilogue: bias + LoRA, scatter to [N,H,L,HD]
    const int t = c0 >> 10;                               // 0=q,1=k,2=v
    const float* Bl = (t == 0) ? Bq : ((t == 1) ? Bk : Bv);
    float* dst = (t == 0) ? g_q : ((t == 1) ? g_k : g_v);
    const int oc0 = c0 & 1023;
    const int h0 = oc0 >> 6;
    const int d0 = tx << 2;
#pragma unroll
    for (int i = 0; i < 8; i++) {
        const int row = r0 + (ty << 2) + (i & 3) + ((i >> 2) << 6);
        const int n = row >> 10, l = row & 1023;
        const float* xr = g_xa + row * 24 + t * 8;
        float xa[8];
#pragma unroll
        for (int r = 0; r < 8; r++) xa[r] = xr[r];
#pragma unroll
        for (int jh = 0; jh < 2; jh++) {
            const int h = h0 + jh;
            float vals[4];
#pragma unroll
            for (int jp = 0; jp < 2; jp++) {
                float lo, hi;
                unpack2(lo, hi, acc[i][jh * 2 + jp]);
                vals[jp * 2 + 0] = lo;
                vals[jp * 2 + 1] = hi;
            }
#pragma unroll
            for (int j = 0; j < 4; j++) {
                const int col  = c0 + jh * 64 + d0 + j;   // global qkv column (bias)
                const int ocol = oc0 + jh * 64 + d0 + j;  // local column within type (LoRA B)
                const float* Br = Bl + (size_t)ocol * 8;
                float lo = 0.f;
#pragma unroll
                for (int r = 0; r < 8; r++) lo += xa[r] * Br[r];
                vals[j] += bias[col] + 2.0f * lo;
            }
            float* drow = dst + (((size_t)n * H_ + h) * L_ + l) * HD_ + d0;
            *(float4*)drow = make_float4(vals[0], vals[1], vals[2], vals[3]);
        }
    }
}

// ---------------------------------------------------------------------------
// K3: in-place L2 normalize rows of 64 (one warp per row); y=0 -> q, y=1 -> k
// ---------------------------------------------------------------------------
__global__ void norm_kernel() {
    float* g = blockIdx.y ? g_k : g_q;
    const int row = blockIdx.x * 8 + (threadIdx.x >> 5);
    const int lane = threadIdx.x & 31;
    float2* p = (float2*)(g + (size_t)row * HD_) + lane;
    float2 v = *p;
    float s = v.x * v.x + v.y * v.y;
#pragma unroll
    for (int o = 16; o > 0; o >>= 1) s += __shfl_xor_sync(0xffffffffu, s, o);
    const float inv = 1.0f / fmaxf(sqrtf(s), 1e-12f);
    v.x *= inv; v.y *= inv;
    *p = v;
}

// ---------------------------------------------------------------------------
// K4: flash attention. 256 threads, 64q x 64k tiles, 4x4 micro-tile, f32x2.
// smem: Qs[64d][68] | KP (K^T [64d][68], then P row-major [64q][68]) | Vs[64l][68]
// ---------------------------------------------------------------------------
#define ATTN_SMEM_BYTES (3 * 64 * 68 * 4)
__global__ void __launch_bounds__(256, 2) attn_kernel(const float* __restrict__ logit_scale) {
    extern __shared__ float sm[];
    float* Qs = sm;
    float* KP = sm + 64 * 68;
    float* Vs = sm + 2 * 64 * 68;

    const int nh = blockIdx.y;         // n*16 + h
    const int qt = blockIdx.x;         // q tile
    const float* Qb = g_q + ((size_t)nh * L_ + qt * 64) * HD_;
    const float* Kb = g_k + (size_t)nh * L_ * HD_;
    const float* Vb = g_v + (size_t)nh * L_ * HD_;
    const float scale = expf(fminf(logit_scale[nh & 15], 4.6051702f));

    const int tid = threadIdx.x;
    const int tx = tid & 15, ty = tid >> 4;       // tx: 4 k-cols, ty: 4 q-rows
    const int lr = tid >> 2, lk = (tid & 3) << 2; // loader: row 0..63, col base {0,4,8,12}
    const int i0 = ty << 2;                       // this thread's q rows i0..i0+3
    const int j0c = tx << 2;                      // this thread's k/d cols

    // load Q tile (transpose + scale): thread covers cols lk+16*dd of row lr
#pragma unroll
    for (int dd = 0; dd < 4; dd++) {
        const int c = lk + dd * 16;
        float4 q4 = *(const float4*)(Qb + lr * HD_ + c);
        Qs[(c + 0) * 68 + lr] = q4.x * scale;
        Qs[(c + 1) * 68 + lr] = q4.y * scale;
        Qs[(c + 2) * 68 + lr] = q4.z * scale;
        Qs[(c + 3) * 68 + lr] = q4.w * scale;
    }

    ull o_acc[4][2];
    float m_i[4], l_i[4];
#pragma unroll
    for (int i = 0; i < 4; i++) {
        m_i[i] = -1e30f; l_i[i] = 0.f;
        o_acc[i][0] = 0ULL; o_acc[i][1] = 0ULL;
    }

    for (int kt = 0; kt < 16; kt++) {
        float4 kb[4], vb[4];
        const float* Krow = Kb + (size_t)(kt * 64 + lr) * HD_;
        const float* Vrow = Vb + (size_t)(kt * 64 + lr) * HD_;
#pragma unroll
        for (int dd = 0; dd < 4; dd++) {
            kb[dd] = *(const float4*)(Krow + lk + dd * 16);
            vb[dd] = *(const float4*)(Vrow + lk + dd * 16);
        }
        __syncthreads();   // previous PV done with KP(P)/Vs; Qs on iter 0
#pragma unroll
        for (int dd = 0; dd < 4; dd++) {
            const int c = lk + dd * 16;
            KP[(c + 0) * 68 + lr] = kb[dd].x;
            KP[(c + 1) * 68 + lr] = kb[dd].y;
            KP[(c + 2) * 68 + lr] = kb[dd].z;
            KP[(c + 3) * 68 + lr] = kb[dd].w;
            *(float4*)&Vs[lr * 68 + c] = vb[dd];
        }
        __syncthreads();

        // S = Qs^T(scaled) @ K  — 4x4 per thread, f32x2 packed
        ull accS[4][2];
#pragma unroll
        for (int i = 0; i < 4; i++) { accS[i][0] = 0ULL; accS[i][1] = 0ULL; }
#pragma unroll
        for (int kk = 0; kk < 64; kk++) {
            float4 av = *(const float4*)&Qs[kk * 68 + i0];
            ulonglong2 bv = *(const ulonglong2*)&KP[kk * 68 + j0c];
            ull A0 = pack2(av.x), A1 = pack2(av.y), A2 = pack2(av.z), A3 = pack2(av.w);
            fma2(accS[0][0], A0, bv.x); fma2(accS[0][1], A0, bv.y);
            fma2(accS[1][0], A1, bv.x); fma2(accS[1][1], A1, bv.y);
            fma2(accS[2][0], A2, bv.x); fma2(accS[2][1], A2, bv.y);
            fma2(accS[3][0], A3, bv.x); fma2(accS[3][1], A3, bv.y);
        }
        float s[4][4];
#pragma unroll
        for (int i = 0; i < 4; i++) {
            unpack2(s[i][0], s[i][1], accS[i][0]);
            unpack2(s[i][2], s[i][3], accS[i][1]);
        }

        // online softmax (16 threads sharing ty own a row; xor<=8 stays in group)
#pragma unroll
        for (int i = 0; i < 4; i++) {
            float mx = fmaxf(fmaxf(s[i][0], s[i][1]), fmaxf(s[i][2], s[i][3]));
            mx = fmaxf(mx, __shfl_xor_sync(0xffffffffu, mx, 8));
            mx = fmaxf(mx, __shfl_xor_sync(0xffffffffu, mx, 4));
            mx = fmaxf(mx, __shfl_xor_sync(0xffffffffu, mx, 2));
            mx = fmaxf(mx, __shfl_xor_sync(0xffffffffu, mx, 1));
            const float mnew = fmaxf(m_i[i], mx);
            const float corr = __expf(m_i[i] - mnew);
            m_i[i] = mnew;
            float rs = 0.f;
#pragma unroll
            for (int j = 0; j < 4; j++) { s[i][j] = __expf(s[i][j] - mnew); rs += s[i][j]; }
            rs += __shfl_xor_sync(0xffffffffu, rs, 8);
            rs += __shfl_xor_sync(0xffffffffu, rs, 4);
            rs += __shfl_xor_sync(0xffffffffu, rs, 2);
            rs += __shfl_xor_sync(0xffffffffu, rs, 1);
            l_i[i] = l_i[i] * corr + rs;
            const ull c2 = pack2(corr);
            mul2(o_acc[i][0], c2);
            mul2(o_acc[i][1], c2);
        }

        __syncthreads();   // all threads done reading KP as K-tile
        // P row-major: P[qrow][kcol], conflict-free float4 stores
#pragma unroll
        for (int i = 0; i < 4; i++)
            *(float4*)&KP[(i0 + i) * 68 + j0c] =
                make_float4(s[i][0], s[i][1], s[i][2], s[i][3]);
        __syncthreads();

        // O += P @ V  (j blocked by 4; p reads broadcast, v f32x2 pairs)
#pragma unroll
        for (int j0 = 0; j0 < 64; j0 += 4) {
            float4 p4[4];
#pragma unroll
            for (int i = 0; i < 4; i++)
                p4[i] = *(const float4*)&KP[(i0 + i) * 68 + j0];
            ulonglong2 v2[4];
#pragma unroll
            for (int t = 0; t < 4; t++)
                v2[t] = *(const ulonglong2*)&Vs[(j0 + t) * 68 + j0c];
#pragma unroll
            for (int i = 0; i < 4; i++) {
                ull P0 = pack2(p4[i].x), P1 = pack2(p4[i].y);
                ull P2 = pack2(p4[i].z), P3 = pack2(p4[i].w);
                fma2(o_acc[i][0], P0, v2[0].x); fma2(o_acc[i][1], P0, v2[0].y);
                fma2(o_acc[i][0], P1, v2[1].x); fma2(o_acc[i][1], P1, v2[1].y);
                fma2(o_acc[i][0], P2, v2[2].x); fma2(o_acc[i][1], P2, v2[2].y);
                fma2(o_acc[i][0], P3, v2[3].x); fma2(o_acc[i][1], P3, v2[3].y);
            }
        }
    }

    const int n = nh >> 4, h = nh & 15;
#pragma unroll
    for (int i = 0; i < 4; i++) {
        const float inv = 1.0f / l_i[i];
        const int l = qt * 64 + i0 + i;
        float o0, o1, o2, o3;
        unpack2(o0, o1, o_acc[i][0]);
        unpack2(o2, o3, o_acc[i][1]);
        *(float4*)&g_ctx[((size_t)(n * L_ + l)) * C_ + h * 64 + j0c] =
            make_float4(o0 * inv, o1 * inv, o2 * inv, o3 * inv);
    }
}

// ---------------------------------------------------------------------------
// K5: out = ctx @ Wo^T + bo  (same 128x128x16 f32x2 scheme, no LoRA)
// ---------------------------------------------------------------------------
__global__ void __launch_bounds__(256) out_gemm(
        const float* __restrict__ Wo, const float* __restrict__ bo,
        float* __restrict__ out) {
    __shared__ float As[16][132];
    __shared__ float Bs[16][132];
    const int tid = threadIdx.x;
    const int tx = tid & 15, ty = tid >> 4;
    const int r0 = blockIdx.y * 128, c0 = blockIdx.x * 128;
    const int lr = tid >> 2, lk = (tid & 3) << 2;

    ull acc[8][4];
#pragma unroll
    for (int i = 0; i < 8; i++)
#pragma unroll
        for (int j = 0; j < 4; j++) acc[i][j] = 0ULL;

    const float* Ap0 = g_ctx + (size_t)(r0 + lr) * C_ + lk;
    const float* Ap1 = Ap0 + (size_t)64 * C_;
    const float* Bp0 = Wo + (size_t)(c0 + lr) * C_ + lk;
    const float* Bp1 = Bp0 + (size_t)64 * C_;

    for (int k0 = 0; k0 < C_; k0 += 16) {
        float4 a0 = *(const float4*)(Ap0 + k0);
        float4 a1 = *(const float4*)(Ap1 + k0);
        float4 b0 = *(const float4*)(Bp0 + k0);
        float4 b1 = *(const float4*)(Bp1 + k0);
        __syncthreads();
        As[lk + 0][lr] = a0.x; As[lk + 1][lr] = a0.y;
        As[lk + 2][lr] = a0.z; As[lk + 3][lr] = a0.w;
        As[lk + 0][lr + 64] = a1.x; As[lk + 1][lr + 64] = a1.y;
        As[lk + 2][lr + 64] = a1.z; As[lk + 3][lr + 64] = a1.w;
        Bs[lk + 0][lr] = b0.x; Bs[lk + 1][lr] = b0.y;
        Bs[lk + 2][lr] = b0.z; Bs[lk + 3][lr] = b0.w;
        Bs[lk + 0][lr + 64] = b1.x; Bs[lk + 1][lr + 64] = b1.y;
        Bs[lk + 2][lr + 64] = b1.z; Bs[lk + 3][lr + 64] = b1.w;
        __syncthreads();
#pragma unroll
        for (int kk = 0; kk < 16; kk++) {
            float4 av0 = *(const float4*)&As[kk][ty << 2];
            float4 av1 = *(const float4*)&As[kk][(ty << 2) + 64];
            ulonglong2 bv0 = *(const ulonglong2*)&Bs[kk][tx << 2];
            ulonglong2 bv1 = *(const ulonglong2*)&Bs[kk][(tx << 2) + 64];
            ull A[8];
            A[0] = pack2(av0.x); A[1] = pack2(av0.y);
            A[2] = pack2(av0.z); A[3] = pack2(av0.w);
            A[4] = pack2(av1.x); A[5] = pack2(av1.y);
            A[6] = pack2(av1.z); A[7] = pack2(av1.w);
#pragma unroll
            for (int i = 0; i < 8; i++) {
                fma2(acc[i][0], A[i], bv0.x);
                fma2(acc[i][1], A[i], bv0.y);
                fma2(acc[i][2], A[i], bv1.x);
                fma2(acc[i][3], A[i], bv1.y);
            }
        }
    }
#pragma unroll
    for (int i = 0; i < 8; i++) {
        const int row = r0 + (ty << 2) + (i & 3) + ((i >> 2) << 6);
#pragma unroll
        for (int jh = 0; jh < 2; jh++) {
            const int col = c0 + jh * 64 + (tx << 2);
            float vals[4];
#pragma unroll
            for (int jp = 0; jp < 2; jp++) {
                float lo, hi;
                unpack2(lo, hi, acc[i][jh * 2 + jp]);
                vals[jp * 2 + 0] = lo;
                vals[jp * 2 + 1] = hi;
            }
#pragma unroll
            for (int j = 0; j < 4; j++) vals[j] += bo[col + j];
            *(float4*)&out[(size_t)row * C_ + col] =
                make_float4(vals[0], vals[1], vals[2], vals[3]);
        }
    }
}

// ---------------------------------------------------------------------------
extern "C" void kernel_launch(void* const* d_in, const int* in_sizes, int n_in,
                              void* d_out, int out_size) {
    (void)in_sizes; (void)n_in; (void)out_size;
    const float* x    = (const float*)d_in[0];
    const float* W    = (const float*)d_in[1];
    const float* bias = (const float*)d_in[2];
    const float* Aq   = (const float*)d_in[3];
    const float* Bq   = (const float*)d_in[4];
    const float* Ak   = (const float*)d_in[5];
    const float* Bk   = (const float*)d_in[6];
    const float* Av   = (const float*)d_in[7];
    const float* Bv   = (const float*)d_in[8];
    const float* ls   = (const float*)d_in[9];
    const float* Wo   = (const float*)d_in[10];
    const float* bo   = (const float*)d_in[11];
    float* out = (float*)d_out;

    cudaFuncSetAttribute(attn_kernel, cudaFuncAttributeMaxDynamicSharedMemorySize,
                         ATTN_SMEM_BYTES);

    xa_kernel<<<N_ * L_ / 8, 256>>>(x, Aq, Ak, Av);
    qkv_gemm<<<dim3(24, 32), 256>>>(x, W, bias, Bq, Bk, Bv);
    norm_kernel<<<dim3((N_ * H_ * L_) / 8, 2), 256>>>();
    attn_kernel<<<dim3(16, 64), 256, ATTN_SMEM_BYTES>>>(ls);
    out_gemm<<<dim3(8, 32), 256>>>(Wo, bo, out);
}

// round 16
// speedup vs baseline: 1.7485x; 1.4096x over previous
#include <cuda_runtime.h>
#include <cuda_bf16.h>
#include <math.h>
#include <cstdint>

#define N_ 4
#define L_ 1024
#define C_ 1024
#define H_ 16
#define HD_ 64
#define R_ 8

typedef unsigned long long ull;

// ------------------------- scratch (__device__ globals) ---------------------
__device__ float g_xa[N_ * L_ * 24];
__device__ float g_q[N_ * H_ * L_ * HD_];
__device__ float g_k[N_ * H_ * L_ * HD_];
__device__ float g_v[N_ * H_ * L_ * HD_];
__device__ float g_ctx[N_ * L_ * C_];
__device__ __nv_bfloat16 g_xh[N_ * L_ * C_], g_xl[N_ * L_ * C_];
__device__ __nv_bfloat16 g_wh[3 * C_ * C_], g_wl[3 * C_ * C_];
__device__ __nv_bfloat16 g_oh[C_ * C_], g_ol[C_ * C_];
__device__ __nv_bfloat16 g_ch[N_ * L_ * C_], g_cl[N_ * L_ * C_];

// ------------------------- f32x2 helpers (attn) -----------------------------
__device__ __forceinline__ void fma2(ull& d, ull a, ull b) {
    asm("fma.rn.f32x2 %0, %1, %2, %0;" : "+l"(d) : "l"(a), "l"(b));
}
__device__ __forceinline__ void mul2(ull& d, ull b) {
    asm("mul.rn.f32x2 %0, %0, %1;" : "+l"(d) : "l"(b));
}
__device__ __forceinline__ ull pack2(float x) {
    ull r; asm("mov.b64 %0, {%1, %1};" : "=l"(r) : "f"(x)); return r;
}
__device__ __forceinline__ void unpack2(float& lo, float& hi, ull v) {
    asm("mov.b64 {%0, %1}, %2;" : "=f"(lo), "=f"(hi) : "l"(v));
}

// ------------------------- mma.sync bf16 helper -----------------------------
__device__ __forceinline__ void mma16816(float* d, const uint32_t* a,
                                         uint32_t b0, uint32_t b1) {
    asm volatile(
        "mma.sync.aligned.m16n8k16.row.col.f32.bf16.bf16.f32 "
        "{%0,%1,%2,%3}, {%4,%5,%6,%7}, {%8,%9}, {%0,%1,%2,%3};"
        : "+f"(d[0]), "+f"(d[1]), "+f"(d[2]), "+f"(d[3])
        : "r"(a[0]), "r"(a[1]), "r"(a[2]), "r"(a[3]), "r"(b0), "r"(b1));
}

// smem element layout (bf16 units): 4 tiles of 128 rows x 40 (stride) bf16
#define GS 40
#define E_AH 0
#define E_AL 5120
#define E_BH 10240
#define E_BL 15360
#define GEMM_SMEM_BYTES (40960 + 512 + 4096)   // tiles + bias(128f) + lora(1024f)

// ---------------------------------------------------------------------------
// split: fp32 -> (hi, lo) bf16 pair
// ---------------------------------------------------------------------------
__global__ void split_kernel(const float4* __restrict__ src,
                             __nv_bfloat162* __restrict__ hi,
                             __nv_bfloat162* __restrict__ lo, int n4) {
    int i = blockIdx.x * 256 + threadIdx.x;
    if (i >= n4) return;
    float4 v = src[i];
    __nv_bfloat16 h0 = __float2bfloat16(v.x), h1 = __float2bfloat16(v.y);
    __nv_bfloat16 h2 = __float2bfloat16(v.z), h3 = __float2bfloat16(v.w);
    __nv_bfloat16 l0 = __float2bfloat16(v.x - __bfloat162float(h0));
    __nv_bfloat16 l1 = __float2bfloat16(v.y - __bfloat162float(h1));
    __nv_bfloat16 l2 = __float2bfloat16(v.z - __bfloat162float(h2));
    __nv_bfloat16 l3 = __float2bfloat16(v.w - __bfloat162float(h3));
    hi[2 * i]     = __nv_bfloat162(h0, h1);
    hi[2 * i + 1] = __nv_bfloat162(h2, h3);
    lo[2 * i]     = __nv_bfloat162(l0, l1);
    lo[2 * i + 1] = __nv_bfloat162(l2, l3);
}
__global__ void split_ctx_kernel() {
    int i = blockIdx.x * 256 + threadIdx.x;
    float4 v = ((const float4*)g_ctx)[i];
    __nv_bfloat16 h0 = __float2bfloat16(v.x), h1 = __float2bfloat16(v.y);
    __nv_bfloat16 h2 = __float2bfloat16(v.z), h3 = __float2bfloat16(v.w);
    __nv_bfloat16 l0 = __float2bfloat16(v.x - __bfloat162float(h0));
    __nv_bfloat16 l1 = __float2bfloat16(v.y - __bfloat162float(h1));
    __nv_bfloat16 l2 = __float2bfloat16(v.z - __bfloat162float(h2));
    __nv_bfloat16 l3 = __float2bfloat16(v.w - __bfloat162float(h3));
    ((__nv_bfloat162*)g_ch)[2 * i]     = __nv_bfloat162(h0, h1);
    ((__nv_bfloat162*)g_ch)[2 * i + 1] = __nv_bfloat162(h2, h3);
    ((__nv_bfloat162*)g_cl)[2 * i]     = __nv_bfloat162(l0, l1);
    ((__nv_bfloat162*)g_cl)[2 * i + 1] = __nv_bfloat162(l2, l3);
}

// ---------------------------------------------------------------------------
// K1: xa = x @ A^T for the three LoRA adapters
// ---------------------------------------------------------------------------
__global__ void xa_kernel(const float* __restrict__ x,
                          const float* __restrict__ Aq,
                          const float* __restrict__ Ak,
                          const float* __restrict__ Av) {
    __shared__ float4 xs4[8][256];
    const int tid = threadIdx.x;
    const int row0 = blockIdx.x * 8;
    const float4* xg = (const float4*)(x + (size_t)row0 * C_);
    for (int i = tid; i < 2048; i += 256) xs4[i >> 8][i & 255] = xg[i];
    __syncthreads();
    const int w = tid >> 5, lane = tid & 31;
#pragma unroll 1
    for (int d = 0; d < 24; d++) {
        const float* A = (d < 8 ? Aq : (d < 16 ? Ak : Av)) + (d & 7) * C_;
        const float4* A4 = (const float4*)A;
        float s = 0.f;
#pragma unroll
        for (int i = 0; i < 8; i++) {
            float4 a = A4[lane + i * 32];
            float4 xv = xs4[w][lane + i * 32];
            s += a.x * xv.x + a.y * xv.y + a.z * xv.z + a.w * xv.w;
        }
#pragma unroll
        for (int o = 16; o > 0; o >>= 1) s += __shfl_xor_sync(0xffffffffu, s, o);
        if (lane == 0) g_xa[(row0 + w) * 24 + d] = s;
    }
}

// ---------------------------------------------------------------------------
// K2: qkv via mma.sync bf16 3-term (Ah*Bh + Ah*Bl + Al*Bh, fp32 accum).
// 128x128 tile, 8 warps (4m x 2n), warp tile 32x64, BK=32, reg-prefetch.
// Epilogue: bias + LoRA, scatter to [N,H,L,HD].
// ---------------------------------------------------------------------------
__global__ void __launch_bounds__(256) qkv_mma(
        const float* __restrict__ bias,
        const float* __restrict__ Bq, const float* __restrict__ Bk,
        const float* __restrict__ Bv) {
    extern __shared__ char smem[];
    __nv_bfloat16* sm = (__nv_bfloat16*)smem;
    float* sb = (float*)(smem + 40960);
    float* sl = sb + 128;

    const int tid = threadIdx.x, wid = tid >> 5, lane = tid & 31;
    const int g = lane >> 2, t4 = lane & 3;
    const int wm = wid & 3, wn = wid >> 2;
    const int c0 = blockIdx.x * 128, r0 = blockIdx.y * 128;
    const int t = c0 >> 10, oc0 = c0 & 1023;
    const float* Blo = (t == 0) ? Bq : ((t == 1) ? Bk : Bv);

    for (int i = tid; i < 128; i += 256) sb[i] = bias[c0 + i];
    for (int i = tid; i < 1024; i += 256) sl[i] = Blo[(size_t)oc0 * 8 + i];

    float d[2][8][4];
#pragma unroll
    for (int mi = 0; mi < 2; mi++)
#pragma unroll
        for (int ni = 0; ni < 8; ni++)
#pragma unroll
            for (int e = 0; e < 4; e++) d[mi][ni][e] = 0.f;

    const int lr0 = tid >> 2, lpc = tid & 3;   // loader: rows lr0, lr0+64; 16B col lpc
    uint4 rAh[2], rAl[2], rBh[2], rBl[2];

#define LOADREGS(K0)                                                          \
    {                                                                         \
        _Pragma("unroll")                                                     \
        for (int j = 0; j < 2; j++) {                                         \
            const int row = lr0 + j * 64;                                     \
            const size_t a = (size_t)(r0 + row) * C_ + (K0) + lpc * 8;        \
            const size_t b = (size_t)(c0 + row) * C_ + (K0) + lpc * 8;        \
            rAh[j] = *(const uint4*)(g_xh + a);                               \
            rAl[j] = *(const uint4*)(g_xl + a);                               \
            rBh[j] = *(const uint4*)(g_wh + b);                               \
            rBl[j] = *(const uint4*)(g_wl + b);                               \
        }                                                                     \
    }

    LOADREGS(0)
    for (int c = 0; c < 32; c++) {
        __syncthreads();
#pragma unroll
        for (int j = 0; j < 2; j++) {
            const int off = (lr0 + j * 64) * GS + lpc * 8;
            *(uint4*)(sm + E_AH + off) = rAh[j];
            *(uint4*)(sm + E_AL + off) = rAl[j];
            *(uint4*)(sm + E_BH + off) = rBh[j];
            *(uint4*)(sm + E_BL + off) = rBl[j];
        }
        __syncthreads();
        if (c < 31) LOADREGS((c + 1) * 32)

#pragma unroll
        for (int ks = 0; ks < 32; ks += 16) {
            uint32_t ah[2][4], al[2][4];
#pragma unroll
            for (int mi = 0; mi < 2; mi++) {
                const int rb = (wm * 32 + mi * 16 + g) * GS + ks + t4 * 2;
                ah[mi][0] = *(const uint32_t*)(sm + E_AH + rb);
                ah[mi][1] = *(const uint32_t*)(sm + E_AH + rb + 8 * GS);
                ah[mi][2] = *(const uint32_t*)(sm + E_AH + rb + 8);
                ah[mi][3] = *(const uint32_t*)(sm + E_AH + rb + 8 * GS + 8);
                al[mi][0] = *(const uint32_t*)(sm + E_AL + rb);
                al[mi][1] = *(const uint32_t*)(sm + E_AL + rb + 8 * GS);
                al[mi][2] = *(const uint32_t*)(sm + E_AL + rb + 8);
                al[mi][3] = *(const uint32_t*)(sm + E_AL + rb + 8 * GS + 8);
            }
#pragma unroll
            for (int ni = 0; ni < 8; ni++) {
                const int nb = (wn * 64 + ni * 8 + g) * GS + ks + t4 * 2;
                const uint32_t bh0 = *(const uint32_t*)(sm + E_BH + nb);
                const uint32_t bh1 = *(const uint32_t*)(sm + E_BH + nb + 8);
                const uint32_t bl0 = *(const uint32_t*)(sm + E_BL + nb);
                const uint32_t bl1 = *(const uint32_t*)(sm + E_BL + nb + 8);
                mma16816(d[0][ni], ah[0], bh0, bh1);
                mma16816(d[1][ni], ah[1], bh0, bh1);
                mma16816(d[0][ni], ah[0], bl0, bl1);
                mma16816(d[1][ni], ah[1], bl0, bl1);
                mma16816(d[0][ni], al[0], bh0, bh1);
                mma16816(d[1][ni], al[1], bh0, bh1);
            }
        }
    }
#undef LOADREGS

    // epilogue: bias + LoRA, scatter
    float xa[2][2][8];
#pragma unroll
    for (int mi = 0; mi < 2; mi++)
#pragma unroll
        for (int rr = 0; rr < 2; rr++) {
            const int row = r0 + wm * 32 + mi * 16 + g + rr * 8;
            const float* xr = g_xa + row * 24 + t * 8;
            float4 p = *(const float4*)xr, q = *(const float4*)(xr + 4);
            xa[mi][rr][0] = p.x; xa[mi][rr][1] = p.y; xa[mi][rr][2] = p.z; xa[mi][rr][3] = p.w;
            xa[mi][rr][4] = q.x; xa[mi][rr][5] = q.y; xa[mi][rr][6] = q.z; xa[mi][rr][7] = q.w;
        }
    float* dst = (t == 0) ? g_q : ((t == 1) ? g_k : g_v);
#pragma unroll
    for (int mi = 0; mi < 2; mi++)
#pragma unroll
        for (int rr = 0; rr < 2; rr++) {
            const int grow = r0 + wm * 32 + mi * 16 + g + rr * 8;
            const int n = grow >> 10, l = grow & 1023;
#pragma unroll
            for (int ni = 0; ni < 8; ni++) {
                const int ocl = wn * 64 + ni * 8 + t4 * 2;
                float lo0 = 0.f, lo1 = 0.f;
                const float* B0 = sl + ocl * 8;
#pragma unroll
                for (int r = 0; r < 8; r++) {
                    lo0 += xa[mi][rr][r] * B0[r];
                    lo1 += xa[mi][rr][r] * B0[8 + r];
                }
                const float v0 = d[mi][ni][rr * 2 + 0] + sb[ocl] + 2.0f * lo0;
                const float v1 = d[mi][ni][rr * 2 + 1] + sb[ocl + 1] + 2.0f * lo1;
                const int h = (oc0 >> 6) + (ocl >> 6);
                const int hd = ocl & 63;
                *(float2*)&dst[(((size_t)n * H_ + h) * L_ + l) * HD_ + hd] =
                    make_float2(v0, v1);
            }
        }
}

// ---------------------------------------------------------------------------
// K5: out = ctx @ Wo^T + bo  (same mma scheme, no LoRA)
// ---------------------------------------------------------------------------
__global__ void __launch_bounds__(256) out_mma(const float* __restrict__ bo,
                                               float* __restrict__ out) {
    extern __shared__ char smem[];
    __nv_bfloat16* sm = (__nv_bfloat16*)smem;
    float* sb = (float*)(smem + 40960);

    const int tid = threadIdx.x, wid = tid >> 5, lane = tid & 31;
    const int g = lane >> 2, t4 = lane & 3;
    const int wm = wid & 3, wn = wid >> 2;
    const int c0 = blockIdx.x * 128, r0 = blockIdx.y * 128;

    for (int i = tid; i < 128; i += 256) sb[i] = bo[c0 + i];

    float d[2][8][4];
#pragma unroll
    for (int mi = 0; mi < 2; mi++)
#pragma unroll
        for (int ni = 0; ni < 8; ni++)
#pragma unroll
            for (int e = 0; e < 4; e++) d[mi][ni][e] = 0.f;

    const int lr0 = tid >> 2, lpc = tid & 3;
    uint4 rAh[2], rAl[2], rBh[2], rBl[2];

#define LOADREGS(K0)                                                          \
    {                                                                         \
        _Pragma("unroll")                                                     \
        for (int j = 0; j < 2; j++) {                                         \
            const int row = lr0 + j * 64;                                     \
            const size_t a = (size_t)(r0 + row) * C_ + (K0) + lpc * 8;        \
            const size_t b = (size_t)(c0 + row) * C_ + (K0) + lpc * 8;        \
            rAh[j] = *(const uint4*)(g_ch + a);                               \
            rAl[j] = *(const uint4*)(g_cl + a);                               \
            rBh[j] = *(const uint4*)(g_oh + b);                               \
            rBl[j] = *(const uint4*)(g_ol + b);                               \
        }                                                                     \
    }

    LOADREGS(0)
    for (int c = 0; c < 32; c++) {
        __syncthreads();
#pragma unroll
        for (int j = 0; j < 2; j++) {
            const int off = (lr0 + j * 64) * GS + lpc * 8;
            *(uint4*)(sm + E_AH + off) = rAh[j];
            *(uint4*)(sm + E_AL + off) = rAl[j];
            *(uint4*)(sm + E_BH + off) = rBh[j];
            *(uint4*)(sm + E_BL + off) = rBl[j];
        }
        __syncthreads();
        if (c < 31) LOADREGS((c + 1) * 32)

#pragma unroll
        for (int ks = 0; ks < 32; ks += 16) {
            uint32_t ah[2][4], al[2][4];
#pragma unroll
            for (int mi = 0; mi < 2; mi++) {
                const int rb = (wm * 32 + mi * 16 + g) * GS + ks + t4 * 2;
                ah[mi][0] = *(const uint32_t*)(sm + E_AH + rb);
                ah[mi][1] = *(const uint32_t*)(sm + E_AH + rb + 8 * GS);
                ah[mi][2] = *(const uint32_t*)(sm + E_AH + rb + 8);
                ah[mi][3] = *(const uint32_t*)(sm + E_AH + rb + 8 * GS + 8);
                al[mi][0] = *(const uint32_t*)(sm + E_AL + rb);
                al[mi][1] = *(const uint32_t*)(sm + E_AL + rb + 8 * GS);
                al[mi][2] = *(const uint32_t*)(sm + E_AL + rb + 8);
                al[mi][3] = *(const uint32_t*)(sm + E_AL + rb + 8 * GS + 8);
            }
#pragma unroll
            for (int ni = 0; ni < 8; ni++) {
                const int nb = (wn * 64 + ni * 8 + g) * GS + ks + t4 * 2;
                const uint32_t bh0 = *(const uint32_t*)(sm + E_BH + nb);
                const uint32_t bh1 = *(const uint32_t*)(sm + E_BH + nb + 8);
                const uint32_t bl0 = *(const uint32_t*)(sm + E_BL + nb);
                const uint32_t bl1 = *(const uint32_t*)(sm + E_BL + nb + 8);
                mma16816(d[0][ni], ah[0], bh0, bh1);
                mma16816(d[1][ni], ah[1], bh0, bh1);
                mma16816(d[0][ni], ah[0], bl0, bl1);
                mma16816(d[1][ni], ah[1], bl0, bl1);
                mma16816(d[0][ni], al[0], bh0, bh1);
                mma16816(d[1][ni], al[1], bh0, bh1);
            }
        }
    }
#undef LOADREGS

#pragma unroll
    for (int mi = 0; mi < 2; mi++)
#pragma unroll
        for (int rr = 0; rr < 2; rr++) {
            const int grow = r0 + wm * 32 + mi * 16 + g + rr * 8;
#pragma unroll
            for (int ni = 0; ni < 8; ni++) {
                const int ocl = wn * 64 + ni * 8 + t4 * 2;
                const float v0 = d[mi][ni][rr * 2 + 0] + sb[ocl];
                const float v1 = d[mi][ni][rr * 2 + 1] + sb[ocl + 1];
                *(float2*)&out[(size_t)grow * C_ + c0 + ocl] = make_float2(v0, v1);
            }
        }
}

// ---------------------------------------------------------------------------
// K3: in-place L2 normalize rows of 64; y=0 -> q, y=1 -> k
// ---------------------------------------------------------------------------
__global__ void norm_kernel() {
    float* g = blockIdx.y ? g_k : g_q;
    const int row = blockIdx.x * 8 + (threadIdx.x >> 5);
    const int lane = threadIdx.x & 31;
    float2* p = (float2*)(g + (size_t)row * HD_) + lane;
    float2 v = *p;
    float s = v.x * v.x + v.y * v.y;
#pragma unroll
    for (int o = 16; o > 0; o >>= 1) s += __shfl_xor_sync(0xffffffffu, s, o);
    const float inv = 1.0f / fmaxf(sqrtf(s), 1e-12f);
    v.x *= inv; v.y *= inv;
    *p = v;
}

// ---------------------------------------------------------------------------
// K4: flash attention (unchanged from R9). 256 thr, 64x64 tiles, 4x4, f32x2.
// ---------------------------------------------------------------------------
#define ATTN_SMEM_BYTES (3 * 64 * 68 * 4)
__global__ void __launch_bounds__(256, 2) attn_kernel(const float* __restrict__ logit_scale) {
    extern __shared__ float smf[];
    float* Qs = smf;
    float* KP = smf + 64 * 68;
    float* Vs = smf + 2 * 64 * 68;

    const int nh = blockIdx.y;
    const int qt = blockIdx.x;
    const float* Qb = g_q + ((size_t)nh * L_ + qt * 64) * HD_;
    const float* Kb = g_k + (size_t)nh * L_ * HD_;
    const float* Vb = g_v + (size_t)nh * L_ * HD_;
    const float scale = expf(fminf(logit_scale[nh & 15], 4.6051702f));

    const int tid = threadIdx.x;
    const int tx = tid & 15, ty = tid >> 4;
    const int lr = tid >> 2, lk = (tid & 3) << 2;
    const int i0 = ty << 2;
    const int j0c = tx << 2;

#pragma unroll
    for (int dd = 0; dd < 4; dd++) {
        const int c = lk + dd * 16;
        float4 q4 = *(const float4*)(Qb + lr * HD_ + c);
        Qs[(c + 0) * 68 + lr] = q4.x * scale;
        Qs[(c + 1) * 68 + lr] = q4.y * scale;
        Qs[(c + 2) * 68 + lr] = q4.z * scale;
        Qs[(c + 3) * 68 + lr] = q4.w * scale;
    }

    ull o_acc[4][2];
    float m_i[4], l_i[4];
#pragma unroll
    for (int i = 0; i < 4; i++) {
        m_i[i] = -1e30f; l_i[i] = 0.f;
        o_acc[i][0] = 0ULL; o_acc[i][1] = 0ULL;
    }

    for (int kt = 0; kt < 16; kt++) {
        float4 kb[4], vb[4];
        const float* Krow = Kb + (size_t)(kt * 64 + lr) * HD_;
        const float* Vrow = Vb + (size_t)(kt * 64 + lr) * HD_;
#pragma unroll
        for (int dd = 0; dd < 4; dd++) {
            kb[dd] = *(const float4*)(Krow + lk + dd * 16);
            vb[dd] = *(const float4*)(Vrow + lk + dd * 16);
        }
        __syncthreads();
#pragma unroll
        for (int dd = 0; dd < 4; dd++) {
            const int c = lk + dd * 16;
            KP[(c + 0) * 68 + lr] = kb[dd].x;
            KP[(c + 1) * 68 + lr] = kb[dd].y;
            KP[(c + 2) * 68 + lr] = kb[dd].z;
            KP[(c + 3) * 68 + lr] = kb[dd].w;
            *(float4*)&Vs[lr * 68 + c] = vb[dd];
        }
        __syncthreads();

        ull accS[4][2];
#pragma unroll
        for (int i = 0; i < 4; i++) { accS[i][0] = 0ULL; accS[i][1] = 0ULL; }
#pragma unroll
        for (int kk = 0; kk < 64; kk++) {
            float4 av = *(const float4*)&Qs[kk * 68 + i0];
            ulonglong2 bv = *(const ulonglong2*)&KP[kk * 68 + j0c];
            ull A0 = pack2(av.x), A1 = pack2(av.y), A2 = pack2(av.z), A3 = pack2(av.w);
            fma2(accS[0][0], A0, bv.x); fma2(accS[0][1], A0, bv.y);
            fma2(accS[1][0], A1, bv.x); fma2(accS[1][1], A1, bv.y);
            fma2(accS[2][0], A2, bv.x); fma2(accS[2][1], A2, bv.y);
            fma2(accS[3][0], A3, bv.x); fma2(accS[3][1], A3, bv.y);
        }
        float s[4][4];
#pragma unroll
        for (int i = 0; i < 4; i++) {
            unpack2(s[i][0], s[i][1], accS[i][0]);
            unpack2(s[i][2], s[i][3], accS[i][1]);
        }

#pragma unroll
        for (int i = 0; i < 4; i++) {
            float mx = fmaxf(fmaxf(s[i][0], s[i][1]), fmaxf(s[i][2], s[i][3]));
            mx = fmaxf(mx, __shfl_xor_sync(0xffffffffu, mx, 8));
            mx = fmaxf(mx, __shfl_xor_sync(0xffffffffu, mx, 4));
            mx = fmaxf(mx, __shfl_xor_sync(0xffffffffu, mx, 2));
            mx = fmaxf(mx, __shfl_xor_sync(0xffffffffu, mx, 1));
            const float mnew = fmaxf(m_i[i], mx);
            const float corr = __expf(m_i[i] - mnew);
            m_i[i] = mnew;
            float rs = 0.f;
#pragma unroll
            for (int j = 0; j < 4; j++) { s[i][j] = __expf(s[i][j] - mnew); rs += s[i][j]; }
            rs += __shfl_xor_sync(0xffffffffu, rs, 8);
            rs += __shfl_xor_sync(0xffffffffu, rs, 4);
            rs += __shfl_xor_sync(0xffffffffu, rs, 2);
            rs += __shfl_xor_sync(0xffffffffu, rs, 1);
            l_i[i] = l_i[i] * corr + rs;
            const ull c2 = pack2(corr);
            mul2(o_acc[i][0], c2);
            mul2(o_acc[i][1], c2);
        }

        __syncthreads();
#pragma unroll
        for (int i = 0; i < 4; i++)
            *(float4*)&KP[(i0 + i) * 68 + j0c] =
                make_float4(s[i][0], s[i][1], s[i][2], s[i][3]);
        __syncthreads();

#pragma unroll
        for (int j0 = 0; j0 < 64; j0 += 4) {
            float4 p4[4];
#pragma unroll
            for (int i = 0; i < 4; i++)
                p4[i] = *(const float4*)&KP[(i0 + i) * 68 + j0];
            ulonglong2 v2[4];
#pragma unroll
            for (int t = 0; t < 4; t++)
                v2[t] = *(const ulonglong2*)&Vs[(j0 + t) * 68 + j0c];
#pragma unroll
            for (int i = 0; i < 4; i++) {
                ull P0 = pack2(p4[i].x), P1 = pack2(p4[i].y);
                ull P2 = pack2(p4[i].z), P3 = pack2(p4[i].w);
                fma2(o_acc[i][0], P0, v2[0].x); fma2(o_acc[i][1], P0, v2[0].y);
                fma2(o_acc[i][0], P1, v2[1].x); fma2(o_acc[i][1], P1, v2[1].y);
                fma2(o_acc[i][0], P2, v2[2].x); fma2(o_acc[i][1], P2, v2[2].y);
                fma2(o_acc[i][0], P3, v2[3].x); fma2(o_acc[i][1], P3, v2[3].y);
            }
        }
    }

    const int n = nh >> 4, h = nh & 15;
#pragma unroll
    for (int i = 0; i < 4; i++) {
        const float inv = 1.0f / l_i[i];
        const int l = qt * 64 + i0 + i;
        float o0, o1, o2, o3;
        unpack2(o0, o1, o_acc[i][0]);
        unpack2(o2, o3, o_acc[i][1]);
        *(float4*)&g_ctx[((size_t)(n * L_ + l)) * C_ + h * 64 + j0c] =
            make_float4(o0 * inv, o1 * inv, o2 * inv, o3 * inv);
    }
}

// ---------------------------------------------------------------------------
extern "C" void kernel_launch(void* const* d_in, const int* in_sizes, int n_in,
                              void* d_out, int out_size) {
    (void)in_sizes; (void)n_in; (void)out_size;
    const float* x    = (const float*)d_in[0];
    const float* W    = (const float*)d_in[1];
    const float* bias = (const float*)d_in[2];
    const float* Aq   = (const float*)d_in[3];
    const float* Bq   = (const float*)d_in[4];
    const float* Ak   = (const float*)d_in[5];
    const float* Bk   = (const float*)d_in[6];
    const float* Av   = (const float*)d_in[7];
    const float* Bv   = (const float*)d_in[8];
    const float* ls   = (const float*)d_in[9];
    const float* Wo   = (const float*)d_in[10];
    const float* bo   = (const float*)d_in[11];
    float* out = (float*)d_out;

    cudaFuncSetAttribute(attn_kernel, cudaFuncAttributeMaxDynamicSharedMemorySize,
                         ATTN_SMEM_BYTES);
    cudaFuncSetAttribute(qkv_mma, cudaFuncAttributeMaxDynamicSharedMemorySize,
                         GEMM_SMEM_BYTES);
    cudaFuncSetAttribute(out_mma, cudaFuncAttributeMaxDynamicSharedMemorySize,
                         GEMM_SMEM_BYTES);

    __nv_bfloat162 *xh, *xl, *wh, *wl, *oh, *ol;
    cudaGetSymbolAddress((void**)&xh, g_xh);
    cudaGetSymbolAddress((void**)&xl, g_xl);
    cudaGetSymbolAddress((void**)&wh, g_wh);
    cudaGetSymbolAddress((void**)&wl, g_wl);
    cudaGetSymbolAddress((void**)&oh, g_oh);
    cudaGetSymbolAddress((void**)&ol, g_ol);

    split_kernel<<<(N_ * L_ * C_ / 4) / 256, 256>>>((const float4*)x, xh, xl, N_ * L_ * C_ / 4);
    split_kernel<<<(3 * C_ * C_ / 4) / 256, 256>>>((const float4*)W, wh, wl, 3 * C_ * C_ / 4);
    split_kernel<<<(C_ * C_ / 4) / 256, 256>>>((const float4*)Wo, oh, ol, C_ * C_ / 4);
    xa_kernel<<<N_ * L_ / 8, 256>>>(x, Aq, Ak, Av);
    qkv_mma<<<dim3(24, 32), 256, GEMM_SMEM_BYTES>>>(bias, Bq, Bk, Bv);
    norm_kernel<<<dim3((N_ * H_ * L_) / 8, 2), 256>>>();
    attn_kernel<<<dim3(16, 64), 256, ATTN_SMEM_BYTES>>>(ls);
    split_ctx_kernel<<<(N_ * L_ * C_ / 4) / 256, 256>>>();
    out_mma<<<dim3(8, 32), 256, GEMM_SMEM_BYTES>>>(bo, out);
}

// round 17
// speedup vs baseline: 2.3930x; 1.3686x over previous
#include <cuda_runtime.h>
#include <cuda_bf16.h>
#include <cuda_fp16.h>
#include <math.h>
#include <cstdint>

#define N_ 4
#define L_ 1024
#define C_ 1024
#define H_ 16
#define HD_ 64
#define R_ 8

// ------------------------- scratch (__device__ globals) ---------------------
__device__ float g_xa[N_ * L_ * 24];
__device__ float g_q[N_ * H_ * L_ * HD_];
__device__ float g_k[N_ * H_ * L_ * HD_];
__device__ float g_v[N_ * H_ * L_ * HD_];
__device__ float g_ctx[N_ * L_ * C_];
__device__ __nv_bfloat16 g_xh[N_ * L_ * C_], g_xl[N_ * L_ * C_];
__device__ __nv_bfloat16 g_wh[3 * C_ * C_], g_wl[3 * C_ * C_];
__device__ __nv_bfloat16 g_oh[C_ * C_], g_ol[C_ * C_];
__device__ __nv_bfloat16 g_ch[N_ * L_ * C_], g_cl[N_ * L_ * C_];
__device__ __half g_qh[N_ * H_ * L_ * HD_], g_ql[N_ * H_ * L_ * HD_];
__device__ __half g_kh[N_ * H_ * L_ * HD_], g_kl[N_ * H_ * L_ * HD_];
__device__ __half g_vh[N_ * H_ * L_ * HD_], g_vl[N_ * H_ * L_ * HD_];

// ------------------------- mma helpers --------------------------------------
__device__ __forceinline__ void mma16816(float* d, const uint32_t* a,
                                         uint32_t b0, uint32_t b1) {
    asm volatile(
        "mma.sync.aligned.m16n8k16.row.col.f32.bf16.bf16.f32 "
        "{%0,%1,%2,%3}, {%4,%5,%6,%7}, {%8,%9}, {%0,%1,%2,%3};"
        : "+f"(d[0]), "+f"(d[1]), "+f"(d[2]), "+f"(d[3])
        : "r"(a[0]), "r"(a[1]), "r"(a[2]), "r"(a[3]), "r"(b0), "r"(b1));
}
__device__ __forceinline__ void mmaf16(float* d, const uint32_t* a,
                                       uint32_t b0, uint32_t b1) {
    asm volatile(
        "mma.sync.aligned.m16n8k16.row.col.f32.f16.f16.f32 "
        "{%0,%1,%2,%3}, {%4,%5,%6,%7}, {%8,%9}, {%0,%1,%2,%3};"
        : "+f"(d[0]), "+f"(d[1]), "+f"(d[2]), "+f"(d[3])
        : "r"(a[0]), "r"(a[1]), "r"(a[2]), "r"(a[3]), "r"(b0), "r"(b1));
}
__device__ __forceinline__ uint32_t smem_u32(const void* p) {
    uint32_t a;
    asm("{ .reg .u64 t; cvta.to.shared.u64 t, %1; cvt.u32.u64 %0, t; }" : "=r"(a) : "l"(p));
    return a;
}
__device__ __forceinline__ void ldmx4t(uint32_t* r, uint32_t saddr) {
    asm volatile("ldmatrix.sync.aligned.m8n8.x4.trans.shared.b16 {%0,%1,%2,%3}, [%4];"
        : "=r"(r[0]), "=r"(r[1]), "=r"(r[2]), "=r"(r[3]) : "r"(saddr));
}

// GEMM smem layout (bf16 units): 4 tiles of 128 rows x 40 stride
#define GS 40
#define E_AH 0
#define E_AL 5120
#define E_BH 10240
#define E_BL 15360
#define GEMM_SMEM_BYTES (40960 + 512 + 4096)

// ---------------------------------------------------------------------------
// split: fp32 -> (hi, lo) bf16 pair
// ---------------------------------------------------------------------------
__global__ void split_kernel(const float4* __restrict__ src,
                             __nv_bfloat162* __restrict__ hi,
                             __nv_bfloat162* __restrict__ lo, int n4) {
    int i = blockIdx.x * 256 + threadIdx.x;
    if (i >= n4) return;
    float4 v = src[i];
    __nv_bfloat16 h0 = __float2bfloat16(v.x), h1 = __float2bfloat16(v.y);
    __nv_bfloat16 h2 = __float2bfloat16(v.z), h3 = __float2bfloat16(v.w);
    __nv_bfloat16 l0 = __float2bfloat16(v.x - __bfloat162float(h0));
    __nv_bfloat16 l1 = __float2bfloat16(v.y - __bfloat162float(h1));
    __nv_bfloat16 l2 = __float2bfloat16(v.z - __bfloat162float(h2));
    __nv_bfloat16 l3 = __float2bfloat16(v.w - __bfloat162float(h3));
    hi[2 * i]     = __nv_bfloat162(h0, h1);
    hi[2 * i + 1] = __nv_bfloat162(h2, h3);
    lo[2 * i]     = __nv_bfloat162(l0, l1);
    lo[2 * i + 1] = __nv_bfloat162(l2, l3);
}
__global__ void split_ctx_kernel() {
    int i = blockIdx.x * 256 + threadIdx.x;
    float4 v = ((const float4*)g_ctx)[i];
    __nv_bfloat16 h0 = __float2bfloat16(v.x), h1 = __float2bfloat16(v.y);
    __nv_bfloat16 h2 = __float2bfloat16(v.z), h3 = __float2bfloat16(v.w);
    __nv_bfloat16 l0 = __float2bfloat16(v.x - __bfloat162float(h0));
    __nv_bfloat16 l1 = __float2bfloat16(v.y - __bfloat162float(h1));
    __nv_bfloat16 l2 = __float2bfloat16(v.z - __bfloat162float(h2));
    __nv_bfloat16 l3 = __float2bfloat16(v.w - __bfloat162float(h3));
    ((__nv_bfloat162*)g_ch)[2 * i]     = __nv_bfloat162(h0, h1);
    ((__nv_bfloat162*)g_ch)[2 * i + 1] = __nv_bfloat162(h2, h3);
    ((__nv_bfloat162*)g_cl)[2 * i]     = __nv_bfloat162(l0, l1);
    ((__nv_bfloat162*)g_cl)[2 * i + 1] = __nv_bfloat162(l2, l3);
}

// ---------------------------------------------------------------------------
// K1: xa = x @ A^T for the three LoRA adapters
// ---------------------------------------------------------------------------
__global__ void xa_kernel(const float* __restrict__ x,
                          const float* __restrict__ Aq,
                          const float* __restrict__ Ak,
                          const float* __restrict__ Av) {
    __shared__ float4 xs4[8][256];
    const int tid = threadIdx.x;
    const int row0 = blockIdx.x * 8;
    const float4* xg = (const float4*)(x + (size_t)row0 * C_);
    for (int i = tid; i < 2048; i += 256) xs4[i >> 8][i & 255] = xg[i];
    __syncthreads();
    const int w = tid >> 5, lane = tid & 31;
#pragma unroll 1
    for (int d = 0; d < 24; d++) {
        const float* A = (d < 8 ? Aq : (d < 16 ? Ak : Av)) + (d & 7) * C_;
        const float4* A4 = (const float4*)A;
        float s = 0.f;
#pragma unroll
        for (int i = 0; i < 8; i++) {
            float4 a = A4[lane + i * 32];
            float4 xv = xs4[w][lane + i * 32];
            s += a.x * xv.x + a.y * xv.y + a.z * xv.z + a.w * xv.w;
        }
#pragma unroll
        for (int o = 16; o > 0; o >>= 1) s += __shfl_xor_sync(0xffffffffu, s, o);
        if (lane == 0) g_xa[(row0 + w) * 24 + d] = s;
    }
}

// ---------------------------------------------------------------------------
// K2: qkv via mma.sync bf16 3-term (unchanged from R16 pass)
// ---------------------------------------------------------------------------
__global__ void __launch_bounds__(256) qkv_mma(
        const float* __restrict__ bias,
        const float* __restrict__ Bq, const float* __restrict__ Bk,
        const float* __restrict__ Bv) {
    extern __shared__ char smem[];
    __nv_bfloat16* sm = (__nv_bfloat16*)smem;
    float* sb = (float*)(smem + 40960);
    float* sl = sb + 128;

    const int tid = threadIdx.x, wid = tid >> 5, lane = tid & 31;
    const int g = lane >> 2, t4 = lane & 3;
    const int wm = wid & 3, wn = wid >> 2;
    const int c0 = blockIdx.x * 128, r0 = blockIdx.y * 128;
    const int t = c0 >> 10, oc0 = c0 & 1023;
    const float* Blo = (t == 0) ? Bq : ((t == 1) ? Bk : Bv);

    for (int i = tid; i < 128; i += 256) sb[i] = bias[c0 + i];
    for (int i = tid; i < 1024; i += 256) sl[i] = Blo[(size_t)oc0 * 8 + i];

    float d[2][8][4];
#pragma unroll
    for (int mi = 0; mi < 2; mi++)
#pragma unroll
        for (int ni = 0; ni < 8; ni++)
#pragma unroll
            for (int e = 0; e < 4; e++) d[mi][ni][e] = 0.f;

    const int lr0 = tid >> 2, lpc = tid & 3;
    uint4 rAh[2], rAl[2], rBh[2], rBl[2];

#define LOADREGS(K0)                                                          \
    {                                                                         \
        _Pragma("unroll")                                                     \
        for (int j = 0; j < 2; j++) {                                         \
            const int row = lr0 + j * 64;                                     \
            const size_t a = (size_t)(r0 + row) * C_ + (K0) + lpc * 8;        \
            const size_t b = (size_t)(c0 + row) * C_ + (K0) + lpc * 8;        \
            rAh[j] = *(const uint4*)(g_xh + a);                               \
            rAl[j] = *(const uint4*)(g_xl + a);                               \
            rBh[j] = *(const uint4*)(g_wh + b);                               \
            rBl[j] = *(const uint4*)(g_wl + b);                               \
        }                                                                     \
    }

    LOADREGS(0)
    for (int c = 0; c < 32; c++) {
        __syncthreads();
#pragma unroll
        for (int j = 0; j < 2; j++) {
            const int off = (lr0 + j * 64) * GS + lpc * 8;
            *(uint4*)(sm + E_AH + off) = rAh[j];
            *(uint4*)(sm + E_AL + off) = rAl[j];
            *(uint4*)(sm + E_BH + off) = rBh[j];
            *(uint4*)(sm + E_BL + off) = rBl[j];
        }
        __syncthreads();
        if (c < 31) LOADREGS((c + 1) * 32)

#pragma unroll
        for (int ks = 0; ks < 32; ks += 16) {
            uint32_t ah[2][4], al[2][4];
#pragma unroll
            for (int mi = 0; mi < 2; mi++) {
                const int rb = (wm * 32 + mi * 16 + g) * GS + ks + t4 * 2;
                ah[mi][0] = *(const uint32_t*)(sm + E_AH + rb);
                ah[mi][1] = *(const uint32_t*)(sm + E_AH + rb + 8 * GS);
                ah[mi][2] = *(const uint32_t*)(sm + E_AH + rb + 8);
                ah[mi][3] = *(const uint32_t*)(sm + E_AH + rb + 8 * GS + 8);
                al[mi][0] = *(const uint32_t*)(sm + E_AL + rb);
                al[mi][1] = *(const uint32_t*)(sm + E_AL + rb + 8 * GS);
                al[mi][2] = *(const uint32_t*)(sm + E_AL + rb + 8);
                al[mi][3] = *(const uint32_t*)(sm + E_AL + rb + 8 * GS + 8);
            }
#pragma unroll
            for (int ni = 0; ni < 8; ni++) {
                const int nb = (wn * 64 + ni * 8 + g) * GS + ks + t4 * 2;
                const uint32_t bh0 = *(const uint32_t*)(sm + E_BH + nb);
                const uint32_t bh1 = *(const uint32_t*)(sm + E_BH + nb + 8);
                const uint32_t bl0 = *(const uint32_t*)(sm + E_BL + nb);
                const uint32_t bl1 = *(const uint32_t*)(sm + E_BL + nb + 8);
                mma16816(d[0][ni], ah[0], bh0, bh1);
                mma16816(d[1][ni], ah[1], bh0, bh1);
                mma16816(d[0][ni], ah[0], bl0, bl1);
                mma16816(d[1][ni], ah[1], bl0, bl1);
                mma16816(d[0][ni], al[0], bh0, bh1);
                mma16816(d[1][ni], al[1], bh0, bh1);
            }
        }
    }
#undef LOADREGS

    float xa[2][2][8];
#pragma unroll
    for (int mi = 0; mi < 2; mi++)
#pragma unroll
        for (int rr = 0; rr < 2; rr++) {
            const int row = r0 + wm * 32 + mi * 16 + g + rr * 8;
            const float* xr = g_xa + row * 24 + t * 8;
            float4 p = *(const float4*)xr, q = *(const float4*)(xr + 4);
            xa[mi][rr][0] = p.x; xa[mi][rr][1] = p.y; xa[mi][rr][2] = p.z; xa[mi][rr][3] = p.w;
            xa[mi][rr][4] = q.x; xa[mi][rr][5] = q.y; xa[mi][rr][6] = q.z; xa[mi][rr][7] = q.w;
        }
    float* dst = (t == 0) ? g_q : ((t == 1) ? g_k : g_v);
#pragma unroll
    for (int mi = 0; mi < 2; mi++)
#pragma unroll
        for (int rr = 0; rr < 2; rr++) {
            const int grow = r0 + wm * 32 + mi * 16 + g + rr * 8;
            const int n = grow >> 10, l = grow & 1023;
#pragma unroll
            for (int ni = 0; ni < 8; ni++) {
                const int ocl = wn * 64 + ni * 8 + t4 * 2;
                float lo0 = 0.f, lo1 = 0.f;
                const float* B0 = sl + ocl * 8;
#pragma unroll
                for (int r = 0; r < 8; r++) {
                    lo0 += xa[mi][rr][r] * B0[r];
                    lo1 += xa[mi][rr][r] * B0[8 + r];
                }
                const float v0 = d[mi][ni][rr * 2 + 0] + sb[ocl] + 2.0f * lo0;
                const float v1 = d[mi][ni][rr * 2 + 1] + sb[ocl + 1] + 2.0f * lo1;
                const int h = (oc0 >> 6) + (ocl >> 6);
                const int hd = ocl & 63;
                *(float2*)&dst[(((size_t)n * H_ + h) * L_ + l) * HD_ + hd] =
                    make_float2(v0, v1);
            }
        }
}

// ---------------------------------------------------------------------------
// K5: out = ctx @ Wo^T + bo  (unchanged from R16 pass)
// ---------------------------------------------------------------------------
__global__ void __launch_bounds__(256) out_mma(const float* __restrict__ bo,
                                               float* __restrict__ out) {
    extern __shared__ char smem[];
    __nv_bfloat16* sm = (__nv_bfloat16*)smem;
    float* sb = (float*)(smem + 40960);

    const int tid = threadIdx.x, wid = tid >> 5, lane = tid & 31;
    const int g = lane >> 2, t4 = lane & 3;
    const int wm = wid & 3, wn = wid >> 2;
    const int c0 = blockIdx.x * 128, r0 = blockIdx.y * 128;

    for (int i = tid; i < 128; i += 256) sb[i] = bo[c0 + i];

    float d[2][8][4];
#pragma unroll
    for (int mi = 0; mi < 2; mi++)
#pragma unroll
        for (int ni = 0; ni < 8; ni++)
#pragma unroll
            for (int e = 0; e < 4; e++) d[mi][ni][e] = 0.f;

    const int lr0 = tid >> 2, lpc = tid & 3;
    uint4 rAh[2], rAl[2], rBh[2], rBl[2];

#define LOADREGS(K0)                                                          \
    {                                                                         \
        _Pragma("unroll")                                                     \
        for (int j = 0; j < 2; j++) {                                         \
            const int row = lr0 + j * 64;                                     \
            const size_t a = (size_t)(r0 + row) * C_ + (K0) + lpc * 8;        \
            const size_t b = (size_t)(c0 + row) * C_ + (K0) + lpc * 8;        \
            rAh[j] = *(const uint4*)(g_ch + a);                               \
            rAl[j] = *(const uint4*)(g_cl + a);                               \
            rBh[j] = *(const uint4*)(g_oh + b);                               \
            rBl[j] = *(const uint4*)(g_ol + b);                               \
        }                                                                     \
    }

    LOADREGS(0)
    for (int c = 0; c < 32; c++) {
        __syncthreads();
#pragma unroll
        for (int j = 0; j < 2; j++) {
            const int off = (lr0 + j * 64) * GS + lpc * 8;
            *(uint4*)(sm + E_AH + off) = rAh[j];
            *(uint4*)(sm + E_AL + off) = rAl[j];
            *(uint4*)(sm + E_BH + off) = rBh[j];
            *(uint4*)(sm + E_BL + off) = rBl[j];
        }
        __syncthreads();
        if (c < 31) LOADREGS((c + 1) * 32)

#pragma unroll
        for (int ks = 0; ks < 32; ks += 16) {
            uint32_t ah[2][4], al[2][4];
#pragma unroll
            for (int mi = 0; mi < 2; mi++) {
                const int rb = (wm * 32 + mi * 16 + g) * GS + ks + t4 * 2;
                ah[mi][0] = *(const uint32_t*)(sm + E_AH + rb);
                ah[mi][1] = *(const uint32_t*)(sm + E_AH + rb + 8 * GS);
                ah[mi][2] = *(const uint32_t*)(sm + E_AH + rb + 8);
                ah[mi][3] = *(const uint32_t*)(sm + E_AH + rb + 8 * GS + 8);
                al[mi][0] = *(const uint32_t*)(sm + E_AL + rb);
                al[mi][1] = *(const uint32_t*)(sm + E_AL + rb + 8 * GS);
                al[mi][2] = *(const uint32_t*)(sm + E_AL + rb + 8);
                al[mi][3] = *(const uint32_t*)(sm + E_AL + rb + 8 * GS + 8);
            }
#pragma unroll
            for (int ni = 0; ni < 8; ni++) {
                const int nb = (wn * 64 + ni * 8 + g) * GS + ks + t4 * 2;
                const uint32_t bh0 = *(const uint32_t*)(sm + E_BH + nb);
                const uint32_t bh1 = *(const uint32_t*)(sm + E_BH + nb + 8);
                const uint32_t bl0 = *(const uint32_t*)(sm + E_BL + nb);
                const uint32_t bl1 = *(const uint32_t*)(sm + E_BL + nb + 8);
                mma16816(d[0][ni], ah[0], bh0, bh1);
                mma16816(d[1][ni], ah[1], bh0, bh1);
                mma16816(d[0][ni], ah[0], bl0, bl1);
                mma16816(d[1][ni], ah[1], bl0, bl1);
                mma16816(d[0][ni], al[0], bh0, bh1);
                mma16816(d[1][ni], al[1], bh0, bh1);
            }
        }
    }
#undef LOADREGS

#pragma unroll
    for (int mi = 0; mi < 2; mi++)
#pragma unroll
        for (int rr = 0; rr < 2; rr++) {
            const int grow = r0 + wm * 32 + mi * 16 + g + rr * 8;
#pragma unroll
            for (int ni = 0; ni < 8; ni++) {
                const int ocl = wn * 64 + ni * 8 + t4 * 2;
                const float v0 = d[mi][ni][rr * 2 + 0] + sb[ocl];
                const float v1 = d[mi][ni][rr * 2 + 1] + sb[ocl + 1];
                *(float2*)&out[(size_t)grow * C_ + c0 + ocl] = make_float2(v0, v1);
            }
        }
}

// ---------------------------------------------------------------------------
// K3: normalize rows of q,k (y=0,1), split v (y=2); emit fp16 hi/lo pairs
// ---------------------------------------------------------------------------
__global__ void norm_split_kernel() {
    const int which = blockIdx.y;
    const float* src = (which == 0) ? g_q : (which == 1) ? g_k : g_v;
    __half* dh = (which == 0) ? g_qh : (which == 1) ? g_kh : g_vh;
    __half* dl = (which == 0) ? g_ql : (which == 1) ? g_kl : g_vl;
    const int row = blockIdx.x * 8 + (threadIdx.x >> 5);
    const int lane = threadIdx.x & 31;
    float2 v = ((const float2*)(src + (size_t)row * HD_))[lane];
    if (which < 2) {
        float s = v.x * v.x + v.y 	* v.y;
#pragma unroll
        for (int o = 16; o > 0; o >>= 1) s += __shfl_xor_sync(0xffffffffu, s, o);
        const float inv = 1.0f / fmaxf(sqrtf(s), 1e-12f);
        v.x *= inv; v.y *= inv;
    }
    __half h0 = __float2half(v.x), h1 = __float2half(v.y);
    __half l0 = __float2half(v.x - __half2float(h0));
    __half l1 = __float2half(v.y - __half2float(h1));
    ((__half2*)(dh + (size_t)row * HD_))[lane] = __halves2half2(h0, h1);
    ((__half2*)(dl + (size_t)row * HD_))[lane] = __halves2half2(l0, l1);
}

// ---------------------------------------------------------------------------
// K4: flash attention via mma.sync fp16 hi/lo.
// Block: 128 q-rows x full head; 8 warps x 16 q-rows; K/V tiles of 64.
// smem (halves, stride 72): Kh Kl Vh Vl [64][72], Ph Pl [128][72]
// ---------------------------------------------------------------------------
#define AGS 72
#define ATTN2_SMEM_BYTES ((4 * 64 * AGS + 2 * 128 * AGS) * 2)
__global__ void __launch_bounds__(256) attn_mma(const float* __restrict__ logit_scale) {
    extern __shared__ char sm8[];
    __half* Kh = (__half*)sm8;
    __half* Kl = Kh + 64 * AGS;
    __half* Vh = Kl + 64 * AGS;
    __half* Vl = Vh + 64 * AGS;
    __half* Ph = Vl + 64 * AGS;
    __half* Pl = Ph + 128 * AGS;

    const int nh = blockIdx.y, qt = blockIdx.x;
    const float scale = expf(fminf(logit_scale[nh & 15], 4.6051702f));
    const int tid = threadIdx.x, wid = tid >> 5, lane = tid & 31;
    const int g = lane >> 2, t4 = lane & 3;
    const size_t base = (size_t)nh * L_ * HD_;
    const int q0 = qt * 128 + wid * 16;

    // Q A-frags straight from gmem (fp16 hi/lo)
    uint32_t qa[2][4][4];
    {
        const __half* qs[2] = { g_qh + base, g_ql + base };
#pragma unroll
        for (int hl = 0; hl < 2; hl++)
#pragma unroll
            for (int ks = 0; ks < 4; ks++) {
                const __half* p0 = qs[hl] + (size_t)(q0 + g) * HD_ + ks * 16 + t4 * 2;
                qa[hl][ks][0] = *(const uint32_t*)p0;
                qa[hl][ks][1] = *(const uint32_t*)(p0 + 8 * HD_);
                qa[hl][ks][2] = *(const uint32_t*)(p0 + 8);
                qa[hl][ks][3] = *(const uint32_t*)(p0 + 8 * HD_ + 8);
            }
    }

    float o[8][4], m_i[2], l_i[2];
#pragma unroll
    for (int ni = 0; ni < 8; ni++)
#pragma unroll
        for (int e = 0; e < 4; e++) o[ni][e] = 0.f;
    m_i[0] = m_i[1] = -1e30f;
    l_i[0] = l_i[1] = 0.f;

    const int lrow = tid >> 2, lseg = tid & 3;

    for (int kt = 0; kt < 16; kt++) {
        // stage K/V tile (natural [l][d], fp16 hi/lo)
        const size_t src = base + (size_t)(kt * 64 + lrow) * HD_ + lseg * 16;
        uint4 kh0 = *(const uint4*)(g_kh + src), kh1 = *(const uint4*)(g_kh + src + 8);
        uint4 kl0 = *(const uint4*)(g_kl + src), kl1 = *(const uint4*)(g_kl + src + 8);
        uint4 vh0 = *(const uint4*)(g_vh + src), vh1 = *(const uint4*)(g_vh + src + 8);
        uint4 vl0 = *(const uint4*)(g_vl + src), vl1 = *(const uint4*)(g_vl + src + 8);
        __syncthreads();   // prior tile's PV reads of Vs done
        {
            const int off = lrow * AGS + lseg * 16;
            *(uint4*)(Kh + off) = kh0; *(uint4*)(Kh + off + 8) = kh1;
            *(uint4*)(Kl + off) = kl0; *(uint4*)(Kl + off + 8) = kl1;
            *(uint4*)(Vh + off) = vh0; *(uint4*)(Vh + off + 8) = vh1;
            *(uint4*)(Vl + off) = vl0; *(uint4*)(Vl + off + 8) = vl1;
        }
        __syncthreads();

        // S = Q K^T  (3-term fp16)
        float s[8][4];
#pragma unroll
        for (int ni = 0; ni < 8; ni++)
#pragma unroll
            for (int e = 0; e < 4; e++) s[ni][e] = 0.f;
#pragma unroll
        for (int ks = 0; ks < 4; ks++)
#pragma unroll
            for (int ni = 0; ni < 8; ni++) {
                const int nb = (ni * 8 + g) * AGS + ks * 16 + t4 * 2;
                const uint32_t bh0 = *(const uint32_t*)(Kh + nb);
                const uint32_t bh1 = *(const uint32_t*)(Kh + nb + 8);
                const uint32_t bl0 = *(const uint32_t*)(Kl + nb);
                const uint32_t bl1 = *(const uint32_t*)(Kl + nb + 8);
                mmaf16(s[ni], qa[0][ks], bh0, bh1);
                mmaf16(s[ni], qa[0][ks], bl0, bl1);
                mmaf16(s[ni], qa[1][ks], bh0, bh1);
            }

        // online softmax (rows g, g+8; quad reduction over t4)
#pragma unroll
        for (int r = 0; r < 2; r++) {
            float mx = -1e30f;
#pragma unroll
            for (int ni = 0; ni < 8; ni++)
                mx = fmaxf(mx, fmaxf(s[ni][r * 2], s[ni][r * 2 + 1]));
            mx = fmaxf(mx, __shfl_xor_sync(0xffffffffu, mx, 1));
            mx = fmaxf(mx, __shfl_xor_sync(0xffffffffu, mx, 2));
            const float mnew = fmaxf(m_i[r], mx * scale);
            const float corr = __expf(m_i[r] - mnew);
            m_i[r] = mnew;
            float rs = 0.f;
#pragma unroll
            for (int ni = 0; ni < 8; ni++) {
                const float p0 = __expf(s[ni][r * 2] * scale - mnew);
                const float p1 = __expf(s[ni][r * 2 + 1] * scale - mnew);
                s[ni][r * 2] = p0; s[ni][r * 2 + 1] = p1;
                rs += p0 + p1;
            }
            rs += __shfl_xor_sync(0xffffffffu, rs, 1);
            rs += __shfl_xor_sync(0xffffffffu, rs, 2);
            l_i[r] = l_i[r] * corr + rs;
#pragma unroll
            for (int ni = 0; ni < 8; ni++) {
                o[ni][r * 2] *= corr;
                o[ni][r * 2 + 1] *= corr;
            }
        }

        // store P (warp-private rows), fp16 hi/lo
        __syncwarp();
#pragma unroll
        for (int ni = 0; ni < 8; ni++)
#pragma unroll
            for (int r = 0; r < 2; r++) {
                const float p0 = s[ni][r * 2], p1 = s[ni][r * 2 + 1];
                const __half h0 = __float2half(p0), h1 = __float2half(p1);
                const __half l0 = __float2half(p0 - __half2float(h0));
                const __half l1 = __float2half(p1 - __half2float(h1));
                const int prow = wid * 16 + g + r * 8;
                *(__half2*)&Ph[prow * AGS + ni * 8 + t4 * 2] = __halves2half2(h0, h1);
                *(__half2*)&Pl[prow * AGS + ni * 8 + t4 * 2] = __halves2half2(l0, l1);
            }
        __syncwarp();

        // O += P V  (3-term fp16; V B-frags via ldmatrix.trans)
#pragma unroll
        for (int ks = 0; ks < 4; ks++) {
            uint32_t pah[4], pal[4];
            const int pb = (wid * 16 + g) * AGS + ks * 16 + t4 * 2;
            pah[0] = *(const uint32_t*)(Ph + pb);
            pah[1] = *(const uint32_t*)(Ph + pb + 8 * AGS);
            pah[2] = *(const uint32_t*)(Ph + pb + 8);
            pah[3] = *(const uint32_t*)(Ph + pb + 8 * AGS + 8);
            pal[0] = *(const uint32_t*)(Pl + pb);
            pal[1] = *(const uint32_t*)(Pl + pb + 8 * AGS);
            pal[2] = *(const uint32_t*)(Pl + pb + 8);
            pal[3] = *(const uint32_t*)(Pl + pb + 8 * AGS + 8);
            const int grp = lane >> 3, li = lane & 7;
            const int vrow = ks * 16 + (grp & 1) * 8 + li;
            const int vcolo = (grp >> 1) * 8;
#pragma unroll
            for (int nd = 0; nd < 4; nd++) {
                uint32_t bh[4], bl[4];
                ldmx4t(bh, smem_u32(Vh + vrow * AGS + nd * 16 + vcolo));
                ldmx4t(bl, smem_u32(Vl + vrow * AGS + nd * 16 + vcolo));
                mmaf16(o[nd * 2],     pah, bh[0], bh[1]);
                mmaf16(o[nd * 2 + 1], pah, bh[2], bh[3]);
                mmaf16(o[nd * 2],     pah, bl[0], bl[1]);
                mmaf16(o[nd * 2 + 1], pah, bl[2], bl[3]);
                mmaf16(o[nd * 2],     pal, bh[0], bh[1]);
                mmaf16(o[nd * 2 + 1], pal, bh[2], bh[3]);
            }
        }
    }

    // epilogue
    const int n = nh >> 4, h = nh & 15;
#pragma unroll
    for (int r = 0; r < 2; r++) {
        const float inv = 1.0f / l_i[r];
        const int l = q0 + g + r * 8;
        float* drow = g_ctx + ((size_t)(n * L_ + l)) * C_ + h * 64;
#pragma unroll
        for (int ni = 0; ni < 8; ni++)
            *(float2*)&drow[ni * 8 + t4 * 2] =
                make_float2(o[ni][r * 2] * inv, o[ni][r * 2 + 1] * inv);
    }
}

// ---------------------------------------------------------------------------
extern "C" void kernel_launch(void* const* d_in, const int* in_sizes, int n_in,
                              void* d_out, int out_size) {
    (void)in_sizes; (void)n_in; (void)out_size;
    const float* x    = (const float*)d_in[0];
    const float* W    = (const float*)d_in[1];
    const float* bias = (const float*)d_in[2];
    const float* Aq   = (const float*)d_in[3];
    const float* Bq   = (const float*)d_in[4];
    const float* Ak   = (const float*)d_in[5];
    const float* Bk   = (const float*)d_in[6];
    const float* Av   = (const float*)d_in[7];
    const float* Bv   = (const float*)d_in[8];
    const float* ls   = (const float*)d_in[9];
    const float* Wo   = (const float*)d_in[10];
    const float* bo   = (const float*)d_in[11];
    float* out = (float*)d_out;

    cudaFuncSetAttribute(qkv_mma, cudaFuncAttributeMaxDynamicSharedMemorySize,
                         GEMM_SMEM_BYTES);
    cudaFuncSetAttribute(out_mma, cudaFuncAttributeMaxDynamicSharedMemorySize,
                         GEMM_SMEM_BYTES);
    cudaFuncSetAttribute(attn_mma, cudaFuncAttributeMaxDynamicSharedMemorySize,
                         ATTN2_SMEM_BYTES);

    __nv_bfloat162 *xh, *xl, *wh, *wl, *oh, *ol;
    cudaGetSymbolAddress((void**)&xh, g_xh);
    cudaGetSymbolAddress((void**)&xl, g_xl);
    cudaGetSymbolAddress((void**)&wh, g_wh);
    cudaGetSymbolAddress((void**)&wl, g_wl);
    cudaGetSymbolAddress((void**)&oh, g_oh);
    cudaGetSymbolAddress((void**)&ol, g_ol);

    split_kernel<<<(N_ * L_ * C_ / 4) / 256, 256>>>((const float4*)x, xh, xl, N_ * L_ * C_ / 4);
    split_kernel<<<(3 * C_ * C_ / 4) / 256, 256>>>((const float4*)W, wh, wl, 3 * C_ * C_ / 4);
    split_kernel<<<(C_ * C_ / 4) / 256, 256>>>((const float4*)Wo, oh, ol, C_ * C_ / 4);
    xa_kernel<<<N_ * L_ / 8, 256>>>(x, Aq, Ak, Av);
    qkv_mma<<<dim3(24, 32), 256, GEMM_SMEM_BYTES>>>(bias, Bq, Bk, Bv);
    norm_split_kernel<<<dim3((N_ * H_ * L_) / 8, 3), 256>>>();
    attn_mma<<<dim3(8, 64), 256, ATTN2_SMEM_BYTES>>>(ls);
    split_ctx_kernel<<<(N_ * L_ * C_ / 4) / 256, 256>>>();
    out_mma<<<dim3(8, 32), 256, GEMM_SMEM_BYTES>>>(bo, out);
}